// round 11
// baseline (speedup 1.0000x reference)
#include <cuda_runtime.h>
#include <cuda_bf16.h>
#include <math.h>
#include <stdint.h>

// Problem constants
#define N_TOK   524288
#define N_WIN   8192
#define P_TOK   64
#define C_DIM   128
#define M_PART  4096
#define MW_CNT  262144
#define A_CNT   131072
#define BL_CNT  65536
#define EPS_LN  1e-6f

// ---------------------------------------------------------------------------
// Scratch (device globals — allocation-free rule)
// ---------------------------------------------------------------------------
__device__ float g_xa[(size_t)A_CNT * C_DIM];
__device__ float g_y[(size_t)A_CNT * C_DIM];
__device__ __nv_bfloat16 g_xp_bf[(size_t)MW_CNT * C_DIM];
__device__ __nv_bfloat16 g_wqkvT[384 * 128];
__device__ __nv_bfloat16 g_wprojT[128 * 128];
__device__ __nv_bfloat16 g_w1T[512 * 128];
__device__ __nv_bfloat16 g_w2T[128 * 512];
__device__ unsigned char g_flag[MW_CNT];
__device__ int g_rank[MW_CNT];
__device__ int g_ipos[MW_CNT];
__device__ int g_winv[N_WIN];
__device__ int g_asyrow[A_CNT];
__device__ unsigned char g_mflag[MW_CNT];
__device__ int g_mrow[MW_CNT];
__device__ int g_mrank[MW_CNT];

// ---------------------------------------------------------------------------
// helpers
// ---------------------------------------------------------------------------
__device__ __forceinline__ void mma_bf16(float c[4], const uint32_t a[4], const uint32_t b[2]) {
    asm volatile(
        "mma.sync.aligned.m16n8k16.row.col.f32.bf16.bf16.f32 "
        "{%0,%1,%2,%3}, {%4,%5,%6,%7}, {%8,%9}, {%0,%1,%2,%3};"
        : "+f"(c[0]), "+f"(c[1]), "+f"(c[2]), "+f"(c[3])
        : "r"(a[0]), "r"(a[1]), "r"(a[2]), "r"(a[3]), "r"(b[0]), "r"(b[1]));
}
__device__ __forceinline__ uint32_t smem_u32(const void* p) {
    uint32_t a;
    asm("{ .reg .u64 t; cvta.to.shared.u64 t, %1; cvt.u32.u64 %0, t; }" : "=r"(a) : "l"(p));
    return a;
}
__device__ __forceinline__ void cp_async16(uint32_t dst, const void* src) {
    asm volatile("cp.async.cg.shared.global [%0], [%1], 16;" :: "r"(dst), "l"(src) : "memory");
}
__device__ __forceinline__ uint32_t packbf(float a, float b) {
    __nv_bfloat162 p = __floats2bfloat162_rn(a, b);
    return *reinterpret_cast<uint32_t*>(&p);
}
__device__ __forceinline__ void warp_sum2(float& s1, float& s2) {
#pragma unroll
    for (int o = 16; o; o >>= 1) {
        s1 += __shfl_xor_sync(0xffffffffu, s1, o);
        s2 += __shfl_xor_sync(0xffffffffu, s2, o);
    }
}
__device__ __forceinline__ void warp_sum4(float& a1, float& a2, float& b1, float& b2) {
#pragma unroll
    for (int o = 16; o; o >>= 1) {
        a1 += __shfl_xor_sync(0xffffffffu, a1, o);
        a2 += __shfl_xor_sync(0xffffffffu, a2, o);
        b1 += __shfl_xor_sync(0xffffffffu, b1, o);
        b2 += __shfl_xor_sync(0xffffffffu, b2, o);
    }
}

// ---------------------------------------------------------------------------
// K0/K1/K2/K2b: init, maps, meta, weight transpose (unchanged)
// ---------------------------------------------------------------------------
__global__ void __launch_bounds__(256) zero_misc_kernel()
{
    int t = blockIdx.x * 256 + threadIdx.x;
    if (t < MW_CNT / 16)
        reinterpret_cast<uint4*>(g_flag)[t] = make_uint4(0u, 0u, 0u, 0u);
    int u = t - MW_CNT / 16;
    if (u >= 0 && u < N_WIN / 4)
        reinterpret_cast<int4*>(g_winv)[u] = make_int4(-1, -1, -1, -1);
}
__global__ void __launch_bounds__(256) set_maps_kernel(
    const int* __restrict__ asy, const int* __restrict__ blk,
    const int* __restrict__ iw, const int* __restrict__ ipart)
{
    int t = blockIdx.x * 256 + threadIdx.x;
    if (t < MW_CNT) g_ipos[ipart[t]] = t;
    if (t < A_CNT) {
        int g = asy[t];
        g_flag[g] = 1;
        g_rank[g] = t;
        g_asyrow[t] = iw[g >> 6] * 64 + (g & 63);
    } else if (t < A_CNT + BL_CNT) {
        g_flag[blk[t - A_CNT]] = 2;
    }
    if (t < M_PART) g_winv[iw[t]] = t;
}
__global__ void __launch_bounds__(256) meta_kernel(
    const int* __restrict__ ipart, const int* __restrict__ iw)
{
    int i = blockIdx.x * 256 + threadIdx.x;
    if (i >= MW_CNT) return;
    int g = ipart[i];
    int f = g_flag[g];
    g_mflag[i] = (unsigned char)f;
    g_mrow[i]  = iw[g >> 6] * 64 + (g & 63);
    g_mrank[i] = (f == 1) ? g_rank[g] : 0;
}
__global__ void __launch_bounds__(256) wtrans_kernel(
    const float* __restrict__ W, __nv_bfloat16* __restrict__ WT, int K, int N)
{
    int idx = blockIdx.x * 256 + threadIdx.x;
    if (idx >= K * N) return;
    int k = idx / N, n = idx - k * N;
    WT[n * K + k] = __float2bfloat16(W[idx]);
}

// ---------------------------------------------------------------------------
// K3: fused LN + scatter (unchanged)
// ---------------------------------------------------------------------------
__global__ void __launch_bounds__(256) ln_kernel(
    const float* __restrict__ x, const float* __restrict__ w,
    const float* __restrict__ b, float* __restrict__ out)
{
    int wglob = blockIdx.x * 8 + (threadIdx.x >> 5);
    int lane  = threadIdx.x & 31;
    int r0 = wglob * 2;
    int r1 = r0 + 1;

    float4 v0 = reinterpret_cast<const float4*>(x + (size_t)r0 * C_DIM)[lane];
    float4 v1 = reinterpret_cast<const float4*>(x + (size_t)r1 * C_DIM)[lane];
    float4 wv = reinterpret_cast<const float4*>(w)[lane];
    float4 bv = reinterpret_cast<const float4*>(b)[lane];

    float a1 = v0.x + v0.y + v0.z + v0.w;
    float a2 = v0.x*v0.x + v0.y*v0.y + v0.z*v0.z + v0.w*v0.w;
    float c1 = v1.x + v1.y + v1.z + v1.w;
    float c2 = v1.x*v1.x + v1.y*v1.y + v1.z*v1.z + v1.w*v1.w;
    warp_sum4(a1, a2, c1, c2);

#pragma unroll
    for (int rr = 0; rr < 2; rr++) {
        int row = rr ? r1 : r0;
        float4 v = rr ? v1 : v0;
        float s1 = rr ? c1 : a1;
        float s2 = rr ? c2 : a2;
        float m = s1 * (1.0f / C_DIM);
        float var = s2 * (1.0f / C_DIM) - m * m;
        float inv = rsqrtf(var + EPS_LN);
        float4 r;
        r.x = (v.x - m) * inv * wv.x + bv.x; r.y = (v.y - m) * inv * wv.y + bv.y;
        r.z = (v.z - m) * inv * wv.z + bv.z; r.w = (v.w - m) * inv * wv.w + bv.w;

        int n = row >> 6, p = row & 63;
        int widx = g_winv[n];
        if (widx < 0) {
            reinterpret_cast<float4*>(out + (size_t)row * C_DIM)[lane] = r;
        } else {
            int g = widx * 64 + p;
            int f = g_flag[g];
            int ipos = g_ipos[g];
            float4 val = r;
            if (f == 2) {
                reinterpret_cast<float4*>(out + (size_t)row * C_DIM)[lane] = r;
            } else if (f == 1) {
                float t1 = r.x + r.y + r.z + r.w;
                float t2 = r.x*r.x + r.y*r.y + r.z*r.z + r.w*r.w;
                warp_sum2(t1, t2);
                float m2 = t1 * (1.0f / C_DIM);
                float var2 = t2 * (1.0f / C_DIM) - m2 * m2;
                float inv2 = rsqrtf(var2 + EPS_LN);
                val.x = (r.x - m2) * inv2 * wv.x + bv.x;
                val.y = (r.y - m2) * inv2 * wv.y + bv.y;
                val.z = (r.z - m2) * inv2 * wv.z + bv.z;
                val.w = (r.w - m2) * inv2 * wv.w + bv.w;
                reinterpret_cast<float4*>(g_xa + (size_t)g_rank[g] * C_DIM)[lane] = val;
            }
            uint2 u;
            u.x = packbf(val.x, val.y);
            u.y = packbf(val.z, val.w);
            *reinterpret_cast<uint2*>(g_xp_bf + (size_t)ipos * C_DIM + lane * 4) = u;
        }
    }
}

// ---------------------------------------------------------------------------
// MEGA 1: QKV GEMM -> attention -> proj GEMM, block = 2 partitions (128 rows)
// SMEM (words): qkvW 128x196 | xpW 128x68 (A, later O) | bW 2x(128x20) |
//               vtW 8x32x36 | kfl 128
// ---------------------------------------------------------------------------
#define QW4 196
#define SAW 68
#define SBW 20
#define BSTG (128 * SBW)
#define MK_QKV_OFF 0
#define MK_XP_OFF  (128 * QW4)
#define MK_B_OFF   (MK_XP_OFF + 128 * SAW)
#define MK_VT_OFF  (MK_B_OFF + 2 * BSTG)
#define MK_KFL_OFF (MK_VT_OFF + 8 * 32 * 36)
#define MK_SMEM_BYTES ((MK_KFL_OFF + 128) * 4)

__global__ void __launch_bounds__(256) qkvattn_kernel(
    const __nv_bfloat16* __restrict__ Ab, const __nv_bfloat16* __restrict__ WqkvT,
    const float* __restrict__ qkvb, const __nv_bfloat16* __restrict__ WprojT,
    const float* __restrict__ projb, const float* __restrict__ g1,
    float* __restrict__ outv)
{
    extern __shared__ uint32_t smu[];
    uint32_t* qw  = smu + MK_QKV_OFF;
    uint32_t* xpw = smu + MK_XP_OFF;
    uint32_t* bW  = smu + MK_B_OFF;
    uint32_t* vtw = smu + MK_VT_OFF;
    int* kfl = (int*)(smu + MK_KFL_OFF);

    int tid  = threadIdx.x;
    int lane = tid & 31;
    int wid  = tid >> 5;
    int wr   = wid >> 1;
    int wc   = wid & 1;
    int g    = lane >> 2;
    int tg   = lane & 3;
    size_t m0 = (size_t)blockIdx.x * 128;

    uint32_t xp_u = smem_u32(xpw);
    uint32_t b_u  = smem_u32(bW);

    if (tid < 128) kfl[tid] = g_mflag[m0 + tid];

    // A panel (xp, 128x128 bf16)
#pragma unroll
    for (int t = 0; t < 8; t++) {
        int idx = tid + t * 256;
        int r = idx >> 4, cc = idx & 15;
        cp_async16(xp_u + (uint32_t)(r * (SAW * 4) + cc * 16),
                   Ab + (m0 + r) * C_DIM + cc * 8);
    }
    auto loadQB = [&](int nc, int kc, int s) {
#pragma unroll
        for (int t = 0; t < 2; t++) {
            int idx = tid + t * 256;
            int r = idx >> 2, cc = idx & 3;
            cp_async16(b_u + (uint32_t)(s * (BSTG * 4) + r * (SBW * 4) + cc * 16),
                       WqkvT + (size_t)(nc * 128 + r) * C_DIM + kc * 32 + cc * 8);
        }
        asm volatile("cp.async.commit_group;" ::: "memory");
    };
    auto loadPB = [&](int kc, int s) {
#pragma unroll
        for (int t = 0; t < 2; t++) {
            int idx = tid + t * 256;
            int r = idx >> 2, cc = idx & 3;
            cp_async16(b_u + (uint32_t)(s * (BSTG * 4) + r * (SBW * 4) + cc * 16),
                       WprojT + (size_t)r * C_DIM + kc * 32 + cc * 8);
        }
        asm volatile("cp.async.commit_group;" ::: "memory");
    };

    loadQB(0, 0, 0);   // includes A txns in the same group

    // ---- Phase 1: QKV GEMM (3 n-chunks of 128) ----
#pragma unroll 1
    for (int nc = 0; nc < 3; nc++) {
        if (nc > 0) loadQB(nc, 0, 0);
        float c[2][8][4];
#pragma unroll
        for (int i = 0; i < 2; i++)
#pragma unroll
            for (int j = 0; j < 8; j++)
#pragma unroll
                for (int q = 0; q < 4; q++) c[i][j][q] = 0.0f;

#pragma unroll
        for (int kc = 0; kc < 4; kc++) {
            int s = kc & 1;
            if (kc < 3) {
                loadQB(nc, kc + 1, s ^ 1);
                asm volatile("cp.async.wait_group 1;" ::: "memory");
            } else {
                asm volatile("cp.async.wait_group 0;" ::: "memory");
            }
            __syncthreads();
            const uint32_t* Bp = bW + s * BSTG;
#pragma unroll
            for (int kk = 0; kk < 2; kk++) {
                int kw = kc * 16 + kk * 8 + tg;
                uint32_t a[2][4], b[8][2];
#pragma unroll
                for (int i = 0; i < 2; i++) {
                    int row = wr * 32 + i * 16 + g;
                    a[i][0] = xpw[row * SAW + kw];
                    a[i][1] = xpw[(row + 8) * SAW + kw];
                    a[i][2] = xpw[row * SAW + kw + 4];
                    a[i][3] = xpw[(row + 8) * SAW + kw + 4];
                }
#pragma unroll
                for (int j = 0; j < 8; j++) {
                    int n = wc * 64 + j * 8 + g;
                    b[j][0] = Bp[n * SBW + kk * 8 + tg];
                    b[j][1] = Bp[n * SBW + kk * 8 + tg + 4];
                }
#pragma unroll
                for (int i = 0; i < 2; i++)
#pragma unroll
                    for (int j = 0; j < 8; j++)
                        mma_bf16(c[i][j], a[i], b[j]);
            }
            __syncthreads();
        }
        // epilogue -> SMEM qkv (bf16)
#pragma unroll
        for (int i = 0; i < 2; i++)
#pragma unroll
            for (int half = 0; half < 2; half++) {
                int row = wr * 32 + i * 16 + g + half * 8;
#pragma unroll
                for (int j = 0; j < 8; j++) {
                    int colg = nc * 128 + wc * 64 + j * 8 + tg * 2;
                    float v0 = c[i][j][half * 2]     + __ldg(&qkvb[colg]);
                    float v1 = c[i][j][half * 2 + 1] + __ldg(&qkvb[colg + 1]);
                    qw[row * QW4 + (colg >> 1)] = packbf(v0, v1);
                }
            }
    }
    __syncthreads();

    // prefetch proj B chunk 0 (overlaps VT build + attention)
    loadPB(0, 0);

    // ---- Phase 2: build VT[p][h][d][key] from V region ----
    {
        const __nv_bfloat16* qb = reinterpret_cast<const __nv_bfloat16*>(qw);
        __nv_bfloat16* vtb = reinterpret_cast<__nv_bfloat16*>(vtw);
        for (int i = tid; i < 16384; i += 256) {
            int key = i & 63;            // 0..63
            int rest = i >> 6;           // 0..255 : p*128 + h*32 + dd
            int p = rest >> 7;
            int hd = rest & 127;
            int h = hd >> 5, dd = hd & 31;
            vtb[(p * 4 + h) * (32 * 72) + dd * 72 + key] =
                qb[(p * 64 + key) * (QW4 * 2) + h * 96 + 64 + dd];
        }
    }
    __syncthreads();

    // ---- Phase 3: attention (loop both partitions) ----
    int h = wid >> 1;
    int rbase = (wid & 1) * 32;
    int qh = h * 48, kh = h * 48 + 16;
    const float scale = 0.17677669529663687f;

    for (int p = 0; p < 2; p++) {
        int rowp = p * 64;
        const uint32_t* vth = vtw + (p * 4 + h) * (32 * 36);

        float c[2][8][4];
#pragma unroll
        for (int i = 0; i < 2; i++)
#pragma unroll
            for (int j = 0; j < 8; j++)
#pragma unroll
                for (int q = 0; q < 4; q++) c[i][j][q] = 0.0f;

#pragma unroll
        for (int kq = 0; kq < 2; kq++) {
            uint32_t a[2][4], b[8][2];
#pragma unroll
            for (int i = 0; i < 2; i++) {
                int row = rowp + rbase + i * 16 + g;
                a[i][0] = qw[row * QW4 + qh + kq * 8 + tg];
                a[i][1] = qw[(row + 8) * QW4 + qh + kq * 8 + tg];
                a[i][2] = qw[row * QW4 + qh + kq * 8 + tg + 4];
                a[i][3] = qw[(row + 8) * QW4 + qh + kq * 8 + tg + 4];
            }
#pragma unroll
            for (int j = 0; j < 8; j++) {
                int n = rowp + j * 8 + g;
                b[j][0] = qw[n * QW4 + kh + kq * 8 + tg];
                b[j][1] = qw[n * QW4 + kh + kq * 8 + tg + 4];
            }
#pragma unroll
            for (int i = 0; i < 2; i++)
#pragma unroll
                for (int j = 0; j < 8; j++)
                    mma_bf16(c[i][j], a[i], b[j]);
        }

        unsigned mask = 0;
#pragma unroll
        for (int j = 0; j < 8; j++)
#pragma unroll
            for (int q = 0; q < 2; q++)
                if (kfl[rowp + j * 8 + 2 * tg + q] == 2) mask |= 1u << (j * 2 + q);

#pragma unroll
        for (int i = 0; i < 2; i++)
#pragma unroll
            for (int sel = 0; sel < 2; sel++) {
                float mx = -1e30f;
#pragma unroll
                for (int j = 0; j < 8; j++)
#pragma unroll
                    for (int q = 0; q < 2; q++) {
                        float v = c[i][j][sel * 2 + q] * scale;
                        if (mask & (1u << (j * 2 + q))) v = -10000.0f;
                        c[i][j][sel * 2 + q] = v;
                        mx = fmaxf(mx, v);
                    }
                mx = fmaxf(mx, __shfl_xor_sync(0xffffffffu, mx, 1));
                mx = fmaxf(mx, __shfl_xor_sync(0xffffffffu, mx, 2));
                float s = 0.0f;
#pragma unroll
                for (int j = 0; j < 8; j++)
#pragma unroll
                    for (int q = 0; q < 2; q++) {
                        float e = __expf(c[i][j][sel * 2 + q] - mx);
                        c[i][j][sel * 2 + q] = e;
                        s += e;
                    }
                s += __shfl_xor_sync(0xffffffffu, s, 1);
                s += __shfl_xor_sync(0xffffffffu, s, 2);
                float rinv = 1.0f / s;
#pragma unroll
                for (int j = 0; j < 8; j++)
#pragma unroll
                    for (int q = 0; q < 2; q++)
                        c[i][j][sel * 2 + q] *= rinv;
            }

        // O = P @ V^T with register-resident P
        float o[2][4][4];
#pragma unroll
        for (int i = 0; i < 2; i++)
#pragma unroll
            for (int j = 0; j < 4; j++)
#pragma unroll
                for (int q = 0; q < 4; q++) o[i][j][q] = 0.0f;

#pragma unroll
        for (int kp = 0; kp < 4; kp++) {
            uint32_t b[4][2];
#pragma unroll
            for (int j = 0; j < 4; j++) {
                int n = j * 8 + g;
                b[j][0] = vth[n * 36 + kp * 8 + tg];
                b[j][1] = vth[n * 36 + kp * 8 + tg + 4];
            }
#pragma unroll
            for (int i = 0; i < 2; i++) {
                uint32_t a[4];
                a[0] = packbf(c[i][2 * kp][0],     c[i][2 * kp][1]);
                a[1] = packbf(c[i][2 * kp][2],     c[i][2 * kp][3]);
                a[2] = packbf(c[i][2 * kp + 1][0], c[i][2 * kp + 1][1]);
                a[3] = packbf(c[i][2 * kp + 1][2], c[i][2 * kp + 1][3]);
#pragma unroll
                for (int j = 0; j < 4; j++)
                    mma_bf16(o[i][j], a, b[j]);
            }
        }

        // write O into xpW (stride SAW) as bf16
#pragma unroll
        for (int i = 0; i < 2; i++)
#pragma unroll
            for (int j = 0; j < 4; j++) {
                int row = rowp + rbase + i * 16 + g;
                int wrd = h * 16 + j * 4 + tg;
                xpw[row * SAW + wrd]       = packbf(o[i][j][0], o[i][j][1]);
                xpw[(row + 8) * SAW + wrd] = packbf(o[i][j][2], o[i][j][3]);
            }
    }
    __syncthreads();

    // ---- Phase 4: proj GEMM (K=128) + scatter epilogue ----
    {
        float c[2][8][4];
#pragma unroll
        for (int i = 0; i < 2; i++)
#pragma unroll
            for (int j = 0; j < 8; j++)
#pragma unroll
                for (int q = 0; q < 4; q++) c[i][j][q] = 0.0f;

#pragma unroll
        for (int kc = 0; kc < 4; kc++) {
            int s = kc & 1;
            if (kc < 3) {
                loadPB(kc + 1, s ^ 1);
                asm volatile("cp.async.wait_group 1;" ::: "memory");
            } else {
                asm volatile("cp.async.wait_group 0;" ::: "memory");
            }
            __syncthreads();
            const uint32_t* Bp = bW + s * BSTG;
#pragma unroll
            for (int kk = 0; kk < 2; kk++) {
                int kw = kc * 16 + kk * 8 + tg;
                uint32_t a[2][4], b[8][2];
#pragma unroll
                for (int i = 0; i < 2; i++) {
                    int row = wr * 32 + i * 16 + g;
                    a[i][0] = xpw[row * SAW + kw];
                    a[i][1] = xpw[(row + 8) * SAW + kw];
                    a[i][2] = xpw[row * SAW + kw + 4];
                    a[i][3] = xpw[(row + 8) * SAW + kw + 4];
                }
#pragma unroll
                for (int j = 0; j < 8; j++) {
                    int n = wc * 64 + j * 8 + g;
                    b[j][0] = Bp[n * SBW + kk * 8 + tg];
                    b[j][1] = Bp[n * SBW + kk * 8 + tg + 4];
                }
#pragma unroll
                for (int i = 0; i < 2; i++)
#pragma unroll
                    for (int j = 0; j < 8; j++)
                        mma_bf16(c[i][j], a[i], b[j]);
            }
            __syncthreads();
        }

#pragma unroll
        for (int i = 0; i < 2; i++)
#pragma unroll
            for (int half = 0; half < 2; half++) {
                size_t grow = m0 + wr * 32 + i * 16 + g + half * 8;
                int f = kfl[grow - m0];
                if (f == 2) continue;
                if (f == 1) {
                    size_t rank = (size_t)g_mrank[grow];
#pragma unroll
                    for (int j = 0; j < 8; j++) {
                        int colg = wc * 64 + j * 8 + tg * 2;
                        float v0 = c[i][j][half * 2]     + __ldg(&projb[colg]);
                        float v1 = c[i][j][half * 2 + 1] + __ldg(&projb[colg + 1]);
                        v0 = g_xa[rank * C_DIM + colg]     + __ldg(&g1[colg]) * v0;
                        v1 = g_xa[rank * C_DIM + colg + 1] + __ldg(&g1[colg + 1]) * v1;
                        *reinterpret_cast<float2*>(g_y + rank * C_DIM + colg) =
                            make_float2(v0, v1);
                    }
                } else {
                    float* dstf = outv + (size_t)g_mrow[grow] * C_DIM;
#pragma unroll
                    for (int j = 0; j < 8; j++) {
                        int colg = wc * 64 + j * 8 + tg * 2;
                        float v0 = c[i][j][half * 2]     + __ldg(&projb[colg]);
                        float v1 = c[i][j][half * 2 + 1] + __ldg(&projb[colg + 1]);
                        *reinterpret_cast<float2*>(dstf + colg) = make_float2(v0, v1);
                    }
                }
            }
    }
}

// ---------------------------------------------------------------------------
// MEGA 2: LN2 -> MLP1(gelu) -> MLP2 + residual scatter, block = 128 asy rows
// SMEM (words): xpW 128x68 (LN2 A) | hW 128x260 | bW 2x(128x20)
// ---------------------------------------------------------------------------
#define SHW 260
#define ML_XP_OFF 0
#define ML_H_OFF  (128 * SAW)
#define ML_B_OFF  (ML_H_OFF + 128 * SHW)
#define ML_SMEM_BYTES ((ML_B_OFF + 2 * BSTG) * 4)

__global__ void __launch_bounds__(256) mlp_kernel(
    const __nv_bfloat16* __restrict__ W1T, const float* __restrict__ b1,
    const __nv_bfloat16* __restrict__ W2T, const float* __restrict__ b2,
    const float* __restrict__ ln2w, const float* __restrict__ ln2b,
    const float* __restrict__ g2, float* __restrict__ outv)
{
    extern __shared__ uint32_t smu[];
    uint32_t* xpw = smu + ML_XP_OFF;
    uint32_t* hw  = smu + ML_H_OFF;
    uint32_t* bW  = smu + ML_B_OFF;

    int tid  = threadIdx.x;
    int lane = tid & 31;
    int wid  = tid >> 5;
    int wr   = wid >> 1;
    int wc   = wid & 1;
    int g    = lane >> 2;
    int tg   = lane & 3;
    size_t m0 = (size_t)blockIdx.x * 128;

    uint32_t b_u = smem_u32(bW);

    auto loadB1 = [&](int nc, int kc, int s) {
#pragma unroll
        for (int t = 0; t < 2; t++) {
            int idx = tid + t * 256;
            int r = idx >> 2, cc = idx & 3;
            cp_async16(b_u + (uint32_t)(s * (BSTG * 4) + r * (SBW * 4) + cc * 16),
                       W1T + (size_t)(nc * 128 + r) * C_DIM + kc * 32 + cc * 8);
        }
        asm volatile("cp.async.commit_group;" ::: "memory");
    };
    auto loadB2 = [&](int kc, int s) {
#pragma unroll
        for (int t = 0; t < 2; t++) {
            int idx = tid + t * 256;
            int r = idx >> 2, cc = idx & 3;
            cp_async16(b_u + (uint32_t)(s * (BSTG * 4) + r * (SBW * 4) + cc * 16),
                       W2T + (size_t)r * 512 + kc * 32 + cc * 8);
        }
        asm volatile("cp.async.commit_group;" ::: "memory");
    };

    loadB1(0, 0, 0);

    // LN2 over g_y -> bf16 A panel (warp per 16 rows)
    {
        float4 wv = reinterpret_cast<const float4*>(ln2w)[lane];
        float4 bv = reinterpret_cast<const float4*>(ln2b)[lane];
        for (int it = 0; it < 16; it++) {
            int r = wid * 16 + it;
            float4 v = reinterpret_cast<const float4*>(g_y + (m0 + r) * C_DIM)[lane];
            float s1 = v.x + v.y + v.z + v.w;
            float s2 = v.x*v.x + v.y*v.y + v.z*v.z + v.w*v.w;
            warp_sum2(s1, s2);
            float m = s1 * (1.0f / C_DIM);
            float var = s2 * (1.0f / C_DIM) - m * m;
            float inv = rsqrtf(var + EPS_LN);
            xpw[r * SAW + lane * 2] = packbf(
                (v.x - m) * inv * wv.x + bv.x, (v.y - m) * inv * wv.y + bv.y);
            xpw[r * SAW + lane * 2 + 1] = packbf(
                (v.z - m) * inv * wv.z + bv.z, (v.w - m) * inv * wv.w + bv.w);
        }
    }

    // ---- MLP1: 4 n-chunks, gelu -> hW ----
#pragma unroll 1
    for (int nc = 0; nc < 4; nc++) {
        if (nc > 0) loadB1(nc, 0, 0);
        float c[2][8][4];
#pragma unroll
        for (int i = 0; i < 2; i++)
#pragma unroll
            for (int j = 0; j < 8; j++)
#pragma unroll
                for (int q = 0; q < 4; q++) c[i][j][q] = 0.0f;

#pragma unroll
        for (int kc = 0; kc < 4; kc++) {
            int s = kc & 1;
            if (kc < 3) {
                loadB1(nc, kc + 1, s ^ 1);
                asm volatile("cp.async.wait_group 1;" ::: "memory");
            } else {
                asm volatile("cp.async.wait_group 0;" ::: "memory");
            }
            __syncthreads();
            const uint32_t* Bp = bW + s * BSTG;
#pragma unroll
            for (int kk = 0; kk < 2; kk++) {
                int kw = kc * 16 + kk * 8 + tg;
                uint32_t a[2][4], b[8][2];
#pragma unroll
                for (int i = 0; i < 2; i++) {
                    int row = wr * 32 + i * 16 + g;
                    a[i][0] = xpw[row * SAW + kw];
                    a[i][1] = xpw[(row + 8) * SAW + kw];
                    a[i][2] = xpw[row * SAW + kw + 4];
                    a[i][3] = xpw[(row + 8) * SAW + kw + 4];
                }
#pragma unroll
                for (int j = 0; j < 8; j++) {
                    int n = wc * 64 + j * 8 + g;
                    b[j][0] = Bp[n * SBW + kk * 8 + tg];
                    b[j][1] = Bp[n * SBW + kk * 8 + tg + 4];
                }
#pragma unroll
                for (int i = 0; i < 2; i++)
#pragma unroll
                    for (int j = 0; j < 8; j++)
                        mma_bf16(c[i][j], a[i], b[j]);
            }
            __syncthreads();
        }
#pragma unroll
        for (int i = 0; i < 2; i++)
#pragma unroll
            for (int half = 0; half < 2; half++) {
                int row = wr * 32 + i * 16 + g + half * 8;
#pragma unroll
                for (int j = 0; j < 8; j++) {
                    int colg = nc * 128 + wc * 64 + j * 8 + tg * 2;
                    float v0 = c[i][j][half * 2]     + __ldg(&b1[colg]);
                    float v1 = c[i][j][half * 2 + 1] + __ldg(&b1[colg + 1]);
                    v0 = 0.5f * v0 * (1.0f + erff(v0 * 0.7071067811865476f));
                    v1 = 0.5f * v1 * (1.0f + erff(v1 * 0.7071067811865476f));
                    hw[row * SHW + (colg >> 1)] = packbf(v0, v1);
                }
            }
    }
    __syncthreads();

    loadB2(0, 0);

    // ---- MLP2: K=512 (16 k-chunks) + residual scatter ----
    {
        float c[2][8][4];
#pragma unroll
        for (int i = 0; i < 2; i++)
#pragma unroll
            for (int j = 0; j < 8; j++)
#pragma unroll
                for (int q = 0; q < 4; q++) c[i][j][q] = 0.0f;

#pragma unroll 1
        for (int kc = 0; kc < 16; kc++) {
            int s = kc & 1;
            if (kc + 1 < 16) {
                loadB2(kc + 1, s ^ 1);
                asm volatile("cp.async.wait_group 1;" ::: "memory");
            } else {
                asm volatile("cp.async.wait_group 0;" ::: "memory");
            }
            __syncthreads();
            const uint32_t* Bp = bW + s * BSTG;
#pragma unroll
            for (int kk = 0; kk < 2; kk++) {
                int kw = kc * 16 + kk * 8 + tg;
                uint32_t a[2][4], b[8][2];
#pragma unroll
                for (int i = 0; i < 2; i++) {
                    int row = wr * 32 + i * 16 + g;
                    a[i][0] = hw[row * SHW + kw];
                    a[i][1] = hw[(row + 8) * SHW + kw];
                    a[i][2] = hw[row * SHW + kw + 4];
                    a[i][3] = hw[(row + 8) * SHW + kw + 4];
                }
#pragma unroll
                for (int j = 0; j < 8; j++) {
                    int n = wc * 64 + j * 8 + g;
                    b[j][0] = Bp[n * SBW + kk * 8 + tg];
                    b[j][1] = Bp[n * SBW + kk * 8 + tg + 4];
                }
#pragma unroll
                for (int i = 0; i < 2; i++)
#pragma unroll
                    for (int j = 0; j < 8; j++)
                        mma_bf16(c[i][j], a[i], b[j]);
            }
            __syncthreads();
        }

#pragma unroll
        for (int i = 0; i < 2; i++)
#pragma unroll
            for (int half = 0; half < 2; half++) {
                size_t grow = m0 + wr * 32 + i * 16 + g + half * 8;
                float* dstf = outv + (size_t)g_asyrow[grow] * C_DIM;
#pragma unroll
                for (int j = 0; j < 8; j++) {
                    int colg = wc * 64 + j * 8 + tg * 2;
                    float v0 = c[i][j][half * 2]     + __ldg(&b2[colg]);
                    float v1 = c[i][j][half * 2 + 1] + __ldg(&b2[colg + 1]);
                    v0 = g_y[grow * C_DIM + colg]     + __ldg(&g2[colg]) * v0;
                    v1 = g_y[grow * C_DIM + colg + 1] + __ldg(&g2[colg + 1]) * v1;
                    *reinterpret_cast<float2*>(dstf + colg) = make_float2(v0, v1);
                }
            }
    }
}

// ---------------------------------------------------------------------------
extern "C" void kernel_launch(void* const* d_in, const int* in_sizes, int n_in,
                              void* d_out, int out_size)
{
    int base = 7;
    if (n_in == 19) base = 5;

    const float* x      = (const float*)d_in[0];
    const int*   iw     = (const int*)d_in[1];
    const int*   ipart  = (const int*)d_in[2];
    const int*   asy    = (const int*)d_in[3];
    const int*   blk    = (const int*)d_in[4];
    const float* ln1w   = (const float*)d_in[base + 0];
    const float* ln1b   = (const float*)d_in[base + 1];
    const float* qkvw   = (const float*)d_in[base + 2];
    const float* qkvb   = (const float*)d_in[base + 3];
    const float* projw  = (const float*)d_in[base + 4];
    const float* projb  = (const float*)d_in[base + 5];
    const float* g1     = (const float*)d_in[base + 6];
    const float* ln2w   = (const float*)d_in[base + 7];
    const float* ln2b   = (const float*)d_in[base + 8];
    const float* w1     = (const float*)d_in[base + 9];
    const float* b1     = (const float*)d_in[base + 10];
    const float* w2     = (const float*)d_in[base + 11];
    const float* b2     = (const float*)d_in[base + 12];
    const float* g2     = (const float*)d_in[base + 13];
    float* out = (float*)d_out;

    __nv_bfloat16 *p_xp, *p_wqkvT, *p_wprojT, *p_w1T, *p_w2T;
    cudaGetSymbolAddress((void**)&p_xp, g_xp_bf);
    cudaGetSymbolAddress((void**)&p_wqkvT, g_wqkvT);
    cudaGetSymbolAddress((void**)&p_wprojT, g_wprojT);
    cudaGetSymbolAddress((void**)&p_w1T, g_w1T);
    cudaGetSymbolAddress((void**)&p_w2T, g_w2T);

    cudaFuncSetAttribute(qkvattn_kernel,
                         cudaFuncAttributeMaxDynamicSharedMemorySize, MK_SMEM_BYTES);
    cudaFuncSetAttribute(mlp_kernel,
                         cudaFuncAttributeMaxDynamicSharedMemorySize, ML_SMEM_BYTES);

    // 0-2. init + maps + meta + weight transposes
    zero_misc_kernel<<<(MW_CNT / 16 + N_WIN / 4 + 255) / 256, 256>>>();
    set_maps_kernel<<<MW_CNT / 256, 256>>>(asy, blk, iw, ipart);
    meta_kernel<<<MW_CNT / 256, 256>>>(ipart, iw);
    wtrans_kernel<<<(128 * 384 + 255) / 256, 256>>>(qkvw, p_wqkvT, 128, 384);
    wtrans_kernel<<<(128 * 128 + 255) / 256, 256>>>(projw, p_wprojT, 128, 128);
    wtrans_kernel<<<(128 * 512 + 255) / 256, 256>>>(w1, p_w1T, 128, 512);
    wtrans_kernel<<<(512 * 128 + 255) / 256, 256>>>(w2, p_w2T, 512, 128);
    // 3. fused LN + double-LN + scatter
    ln_kernel<<<N_TOK / 16, 256>>>(x, ln1w, ln1b, out);
    // 4. QKV -> attention -> proj megakernel
    qkvattn_kernel<<<M_PART / 2, 256, MK_SMEM_BYTES>>>(
        p_xp, p_wqkvT, qkvb, p_wprojT, projb, g1, out);
    // 5. LN2 -> MLP1 -> MLP2 megakernel
    mlp_kernel<<<A_CNT / 128, 256, ML_SMEM_BYTES>>>(
        p_w1T, b1, p_w2T, b2, ln2w, ln2b, g2, out);
}

// round 12
// speedup vs baseline: 1.1402x; 1.1402x over previous
#include <cuda_runtime.h>
#include <cuda_bf16.h>
#include <math.h>
#include <stdint.h>

// Problem constants
#define N_TOK   524288
#define N_WIN   8192
#define P_TOK   64
#define C_DIM   128
#define M_PART  4096
#define MW_CNT  262144
#define A_CNT   131072
#define BL_CNT  65536
#define EPS_LN  1e-6f

// ---------------------------------------------------------------------------
// Scratch (device globals — allocation-free rule)
// ---------------------------------------------------------------------------
__device__ float g_xa[(size_t)A_CNT * C_DIM];
__device__ float g_y[(size_t)A_CNT * C_DIM];
__device__ __nv_bfloat16 g_xp_bf[(size_t)MW_CNT * C_DIM];
__device__ __nv_bfloat16 g_qkv_bf[(size_t)MW_CNT * 384];
__device__ __nv_bfloat16 g_h_bf[(size_t)A_CNT * 512];
__device__ __nv_bfloat16 g_wqkvT[384 * 128];
__device__ __nv_bfloat16 g_wprojT[128 * 128];
__device__ __nv_bfloat16 g_w1T[512 * 128];
__device__ __nv_bfloat16 g_w2T[128 * 512];
__device__ unsigned char g_flag[MW_CNT];
__device__ int g_rank[MW_CNT];
__device__ int g_ipos[MW_CNT];
__device__ int g_winv[N_WIN];
__device__ int g_asyrow[A_CNT];
__device__ unsigned char g_mflag[MW_CNT];
__device__ int g_mrow[MW_CNT];
__device__ int g_mrank[MW_CNT];

// ---------------------------------------------------------------------------
// helpers
// ---------------------------------------------------------------------------
__device__ __forceinline__ void mma_bf16(float c[4], const uint32_t a[4], const uint32_t b[2]) {
    asm volatile(
        "mma.sync.aligned.m16n8k16.row.col.f32.bf16.bf16.f32 "
        "{%0,%1,%2,%3}, {%4,%5,%6,%7}, {%8,%9}, {%0,%1,%2,%3};"
        : "+f"(c[0]), "+f"(c[1]), "+f"(c[2]), "+f"(c[3])
        : "r"(a[0]), "r"(a[1]), "r"(a[2]), "r"(a[3]), "r"(b[0]), "r"(b[1]));
}
__device__ __forceinline__ uint32_t smem_u32(const void* p) {
    uint32_t a;
    asm("{ .reg .u64 t; cvta.to.shared.u64 t, %1; cvt.u32.u64 %0, t; }" : "=r"(a) : "l"(p));
    return a;
}
__device__ __forceinline__ void cp_async16(uint32_t dst, const void* src) {
    asm volatile("cp.async.cg.shared.global [%0], [%1], 16;" :: "r"(dst), "l"(src) : "memory");
}
__device__ __forceinline__ uint32_t packbf(float a, float b) {
    __nv_bfloat162 p = __floats2bfloat162_rn(a, b);
    return *reinterpret_cast<uint32_t*>(&p);
}
__device__ __forceinline__ void warp_sum2(float& s1, float& s2) {
#pragma unroll
    for (int o = 16; o; o >>= 1) {
        s1 += __shfl_xor_sync(0xffffffffu, s1, o);
        s2 += __shfl_xor_sync(0xffffffffu, s2, o);
    }
}
__device__ __forceinline__ void warp_sum4(float& a1, float& a2, float& b1, float& b2) {
#pragma unroll
    for (int o = 16; o; o >>= 1) {
        a1 += __shfl_xor_sync(0xffffffffu, a1, o);
        a2 += __shfl_xor_sync(0xffffffffu, a2, o);
        b1 += __shfl_xor_sync(0xffffffffu, b1, o);
        b2 += __shfl_xor_sync(0xffffffffu, b2, o);
    }
}

// ---------------------------------------------------------------------------
// K0/K1/K2: init, maps, meta
// ---------------------------------------------------------------------------
__global__ void __launch_bounds__(256) zero_misc_kernel()
{
    int t = blockIdx.x * 256 + threadIdx.x;
    if (t < MW_CNT / 16)
        reinterpret_cast<uint4*>(g_flag)[t] = make_uint4(0u, 0u, 0u, 0u);
    int u = t - MW_CNT / 16;
    if (u >= 0 && u < N_WIN / 4)
        reinterpret_cast<int4*>(g_winv)[u] = make_int4(-1, -1, -1, -1);
}
__global__ void __launch_bounds__(256) set_maps_kernel(
    const int* __restrict__ asy, const int* __restrict__ blk,
    const int* __restrict__ iw, const int* __restrict__ ipart)
{
    int t = blockIdx.x * 256 + threadIdx.x;
    if (t < MW_CNT) g_ipos[ipart[t]] = t;
    if (t < A_CNT) {
        int g = asy[t];
        g_flag[g] = 1;
        g_rank[g] = t;
        g_asyrow[t] = iw[g >> 6] * 64 + (g & 63);
    } else if (t < A_CNT + BL_CNT) {
        g_flag[blk[t - A_CNT]] = 2;
    }
    if (t < M_PART) g_winv[iw[t]] = t;
}
__global__ void __launch_bounds__(256) meta_kernel(
    const int* __restrict__ ipart, const int* __restrict__ iw)
{
    int i = blockIdx.x * 256 + threadIdx.x;
    if (i >= MW_CNT) return;
    int g = ipart[i];
    int f = g_flag[g];
    g_mflag[i] = (unsigned char)f;
    g_mrow[i]  = iw[g >> 6] * 64 + (g & 63);
    g_mrank[i] = (f == 1) ? g_rank[g] : 0;
}

// ---------------------------------------------------------------------------
// K2b: ALL weight transposes in one launch (segment select)
// ---------------------------------------------------------------------------
__global__ void __launch_bounds__(256) wtrans_all_kernel(
    const float* __restrict__ qkvw, const float* __restrict__ projw,
    const float* __restrict__ w1, const float* __restrict__ w2,
    __nv_bfloat16* __restrict__ oq, __nv_bfloat16* __restrict__ op,
    __nv_bfloat16* __restrict__ o1, __nv_bfloat16* __restrict__ o2)
{
    int idx = blockIdx.x * 256 + threadIdx.x;
    const float* W; __nv_bfloat16* WT; int K, N, local;
    if (idx < 49152)       { W = qkvw;  WT = oq; K = 128; N = 384; local = idx; }
    else if (idx < 65536)  { W = projw; WT = op; K = 128; N = 128; local = idx - 49152; }
    else if (idx < 131072) { W = w1;    WT = o1; K = 128; N = 512; local = idx - 65536; }
    else                   { W = w2;    WT = o2; K = 512; N = 128; local = idx - 131072; }
    int k = local / N, n = local - k * N;
    WT[n * K + k] = __float2bfloat16(W[(size_t)k * N + n]);
}

// ---------------------------------------------------------------------------
// K3: fused LN + scatter (unchanged)
// ---------------------------------------------------------------------------
__global__ void __launch_bounds__(256) ln_kernel(
    const float* __restrict__ x, const float* __restrict__ w,
    const float* __restrict__ b, float* __restrict__ out)
{
    int wglob = blockIdx.x * 8 + (threadIdx.x >> 5);
    int lane  = threadIdx.x & 31;
    int r0 = wglob * 2;
    int r1 = r0 + 1;

    float4 v0 = reinterpret_cast<const float4*>(x + (size_t)r0 * C_DIM)[lane];
    float4 v1 = reinterpret_cast<const float4*>(x + (size_t)r1 * C_DIM)[lane];
    float4 wv = reinterpret_cast<const float4*>(w)[lane];
    float4 bv = reinterpret_cast<const float4*>(b)[lane];

    float a1 = v0.x + v0.y + v0.z + v0.w;
    float a2 = v0.x*v0.x + v0.y*v0.y + v0.z*v0.z + v0.w*v0.w;
    float c1 = v1.x + v1.y + v1.z + v1.w;
    float c2 = v1.x*v1.x + v1.y*v1.y + v1.z*v1.z + v1.w*v1.w;
    warp_sum4(a1, a2, c1, c2);

#pragma unroll
    for (int rr = 0; rr < 2; rr++) {
        int row = rr ? r1 : r0;
        float4 v = rr ? v1 : v0;
        float s1 = rr ? c1 : a1;
        float s2 = rr ? c2 : a2;
        float m = s1 * (1.0f / C_DIM);
        float var = s2 * (1.0f / C_DIM) - m * m;
        float inv = rsqrtf(var + EPS_LN);
        float4 r;
        r.x = (v.x - m) * inv * wv.x + bv.x; r.y = (v.y - m) * inv * wv.y + bv.y;
        r.z = (v.z - m) * inv * wv.z + bv.z; r.w = (v.w - m) * inv * wv.w + bv.w;

        int n = row >> 6, p = row & 63;
        int widx = g_winv[n];
        if (widx < 0) {
            reinterpret_cast<float4*>(out + (size_t)row * C_DIM)[lane] = r;
        } else {
            int g = widx * 64 + p;
            int f = g_flag[g];
            int ipos = g_ipos[g];
            float4 val = r;
            if (f == 2) {
                reinterpret_cast<float4*>(out + (size_t)row * C_DIM)[lane] = r;
            } else if (f == 1) {
                float t1 = r.x + r.y + r.z + r.w;
                float t2 = r.x*r.x + r.y*r.y + r.z*r.z + r.w*r.w;
                warp_sum2(t1, t2);
                float m2 = t1 * (1.0f / C_DIM);
                float var2 = t2 * (1.0f / C_DIM) - m2 * m2;
                float inv2 = rsqrtf(var2 + EPS_LN);
                val.x = (r.x - m2) * inv2 * wv.x + bv.x;
                val.y = (r.y - m2) * inv2 * wv.y + bv.y;
                val.z = (r.z - m2) * inv2 * wv.z + bv.z;
                val.w = (r.w - m2) * inv2 * wv.w + bv.w;
                reinterpret_cast<float4*>(g_xa + (size_t)g_rank[g] * C_DIM)[lane] = val;
            }
            uint2 u;
            u.x = packbf(val.x, val.y);
            u.y = packbf(val.z, val.w);
            *reinterpret_cast<uint2*>(g_xp_bf + (size_t)ipos * C_DIM + lane * 4) = u;
        }
    }
}

// ---------------------------------------------------------------------------
// GEMM5B: bf16 m16n8k16, A-resident (from R10, unchanged).
//   AMODE 0: bf16 cp.async A panel.  AMODE 1: LN2(g_y) -> bf16 panel.
//   EPI 0: +bias   EPI 2: +bias+gelu
// ---------------------------------------------------------------------------
#define SA5W 68
#define SB5W 20
#define B5WORDS (128 * SB5W)
#define GEMM5B_SMEM_BYTES ((128 * SA5W + 2 * B5WORDS) * 4)

template<int NTOT, int EPI, int AMODE>
__global__ void __launch_bounds__(256) gemm5b_kernel(
    const __nv_bfloat16* __restrict__ Ab, const __nv_bfloat16* __restrict__ WT,
    const float* __restrict__ bias, __nv_bfloat16* __restrict__ outb,
    const float* __restrict__ ln2w, const float* __restrict__ ln2b)
{
    extern __shared__ uint32_t smu[];
    uint32_t* As = smu;
    uint32_t* Bs = smu + 128 * SA5W;

    int tid  = threadIdx.x;
    int lane = tid & 31;
    int wid  = tid >> 5;
    int wr   = wid >> 1;
    int wc   = wid & 1;
    int g    = lane >> 2;
    int tg   = lane & 3;
    size_t m0 = (size_t)blockIdx.x * 128;

    uint32_t as_u = smem_u32(As);
    uint32_t bs_u = smem_u32(Bs);

    auto loadB = [&](int nc, int kc, int s) {
#pragma unroll
        for (int t = 0; t < 2; t++) {
            int idx = tid + t * 256;
            int r = idx >> 2, cc = idx & 3;
            cp_async16(bs_u + (uint32_t)(s * (B5WORDS * 4) + r * (SB5W * 4) + cc * 16),
                       WT + (size_t)(nc * 128 + r) * C_DIM + kc * 32 + cc * 8);
        }
        asm volatile("cp.async.commit_group;" ::: "memory");
    };

    if constexpr (AMODE == 0) {
#pragma unroll
        for (int t = 0; t < 8; t++) {
            int idx = tid + t * 256;
            int r = idx >> 4, cc = idx & 15;
            cp_async16(as_u + (uint32_t)(r * (SA5W * 4) + cc * 16),
                       Ab + (m0 + r) * C_DIM + cc * 8);
        }
        loadB(0, 0, 0);
    } else {
        loadB(0, 0, 0);
        float4 wv = reinterpret_cast<const float4*>(ln2w)[lane];
        float4 bv = reinterpret_cast<const float4*>(ln2b)[lane];
        for (int it = 0; it < 16; it++) {
            int r = wid * 16 + it;
            float4 v = reinterpret_cast<const float4*>(g_y + (m0 + r) * C_DIM)[lane];
            float s1 = v.x + v.y + v.z + v.w;
            float s2 = v.x*v.x + v.y*v.y + v.z*v.z + v.w*v.w;
            warp_sum2(s1, s2);
            float m = s1 * (1.0f / C_DIM);
            float var = s2 * (1.0f / C_DIM) - m * m;
            float inv = rsqrtf(var + EPS_LN);
            As[r * SA5W + lane * 2] = packbf(
                (v.x - m) * inv * wv.x + bv.x, (v.y - m) * inv * wv.y + bv.y);
            As[r * SA5W + lane * 2 + 1] = packbf(
                (v.z - m) * inv * wv.z + bv.z, (v.w - m) * inv * wv.w + bv.w);
        }
    }

    constexpr int NCH = NTOT / 128;
#pragma unroll 1
    for (int nc = 0; nc < NCH; nc++) {
        if (nc > 0) loadB(nc, 0, 0);
        float c[2][8][4];
#pragma unroll
        for (int i = 0; i < 2; i++)
#pragma unroll
            for (int j = 0; j < 8; j++)
#pragma unroll
                for (int q = 0; q < 4; q++) c[i][j][q] = 0.0f;

#pragma unroll
        for (int kc = 0; kc < 4; kc++) {
            int s = kc & 1;
            if (kc < 3) {
                loadB(nc, kc + 1, s ^ 1);
                asm volatile("cp.async.wait_group 1;" ::: "memory");
            } else {
                asm volatile("cp.async.wait_group 0;" ::: "memory");
            }
            __syncthreads();
            const uint32_t* Bp = Bs + s * B5WORDS;
#pragma unroll
            for (int kk = 0; kk < 2; kk++) {
                int kw = kc * 16 + kk * 8 + tg;
                uint32_t a[2][4], b[8][2];
#pragma unroll
                for (int i = 0; i < 2; i++) {
                    int row = wr * 32 + i * 16 + g;
                    a[i][0] = As[row * SA5W + kw];
                    a[i][1] = As[(row + 8) * SA5W + kw];
                    a[i][2] = As[row * SA5W + kw + 4];
                    a[i][3] = As[(row + 8) * SA5W + kw + 4];
                }
#pragma unroll
                for (int j = 0; j < 8; j++) {
                    int n = wc * 64 + j * 8 + g;
                    b[j][0] = Bp[n * SB5W + kk * 8 + tg];
                    b[j][1] = Bp[n * SB5W + kk * 8 + tg + 4];
                }
#pragma unroll
                for (int i = 0; i < 2; i++)
#pragma unroll
                    for (int j = 0; j < 8; j++)
                        mma_bf16(c[i][j], a[i], b[j]);
            }
            __syncthreads();
        }

#pragma unroll
        for (int i = 0; i < 2; i++)
#pragma unroll
            for (int half = 0; half < 2; half++) {
                size_t grow = m0 + wr * 32 + i * 16 + g + half * 8;
#pragma unroll
                for (int j = 0; j < 8; j++) {
                    int colg = nc * 128 + wc * 64 + j * 8 + tg * 2;
                    float v0 = c[i][j][half * 2]     + __ldg(&bias[colg]);
                    float v1 = c[i][j][half * 2 + 1] + __ldg(&bias[colg + 1]);
                    if constexpr (EPI == 2) {
                        v0 = 0.5f * v0 * (1.0f + erff(v0 * 0.7071067811865476f));
                        v1 = 0.5f * v1 * (1.0f + erff(v1 * 0.7071067811865476f));
                    }
                    *reinterpret_cast<__nv_bfloat162*>(outb + grow * NTOT + colg) =
                        __floats2bfloat162_rn(v0, v1);
                }
            }
    }
}

// ---------------------------------------------------------------------------
// GEMM4B (streaming, from R10): only used for MLP2 (KTOT=512, EPI=3)
// ---------------------------------------------------------------------------
#define S4W 20
#define A4WORDS (128 * S4W)
#define B4WORDS (128 * S4W)
#define GEMM4B_SMEM_BYTES ((2 * A4WORDS + 2 * B4WORDS) * 4)

template<int KTOT, int EPI>
__global__ void __launch_bounds__(256) gemm4b_kernel(
    const __nv_bfloat16* __restrict__ Ab, const __nv_bfloat16* __restrict__ WT,
    const float* __restrict__ bias, float* __restrict__ outv,
    const float* __restrict__ evec)
{
    extern __shared__ uint32_t smu[];
    uint32_t* As = smu;
    uint32_t* Bs = smu + 2 * A4WORDS;

    int tid  = threadIdx.x;
    int lane = tid & 31;
    int wid  = tid >> 5;
    int wr   = wid >> 1;
    int wc   = wid & 1;
    int g    = lane >> 2;
    int tg   = lane & 3;
    size_t m0 = (size_t)blockIdx.x * 128;
    constexpr int NC = KTOT / 32;

    uint32_t as_u = smem_u32(As);
    uint32_t bs_u = smem_u32(Bs);

    auto loadAB = [&](int kc, int s) {
#pragma unroll
        for (int t = 0; t < 2; t++) {
            int idx = tid + t * 256;
            int r = idx >> 2, cc = idx & 3;
            cp_async16(as_u + (uint32_t)(s * (A4WORDS * 4) + r * (S4W * 4) + cc * 16),
                       Ab + (m0 + r) * KTOT + kc * 32 + cc * 8);
        }
#pragma unroll
        for (int t = 0; t < 2; t++) {
            int idx = tid + t * 256;
            int r = idx >> 2, cc = idx & 3;
            cp_async16(bs_u + (uint32_t)(s * (B4WORDS * 4) + r * (S4W * 4) + cc * 16),
                       WT + (size_t)r * KTOT + kc * 32 + cc * 8);
        }
        asm volatile("cp.async.commit_group;" ::: "memory");
    };

    float c[2][8][4];
#pragma unroll
    for (int i = 0; i < 2; i++)
#pragma unroll
        for (int j = 0; j < 8; j++)
#pragma unroll
            for (int q = 0; q < 4; q++) c[i][j][q] = 0.0f;

    loadAB(0, 0);
#pragma unroll 1
    for (int kc = 0; kc < NC; kc++) {
        int s = kc & 1;
        if (kc + 1 < NC) {
            loadAB(kc + 1, s ^ 1);
            asm volatile("cp.async.wait_group 1;" ::: "memory");
        } else {
            asm volatile("cp.async.wait_group 0;" ::: "memory");
        }
        __syncthreads();
        const uint32_t* Ap = As + s * A4WORDS;
        const uint32_t* Bp = Bs + s * B4WORDS;
#pragma unroll
        for (int kk = 0; kk < 2; kk++) {
            uint32_t a[2][4], b[8][2];
#pragma unroll
            for (int i = 0; i < 2; i++) {
                int row = wr * 32 + i * 16 + g;
                a[i][0] = Ap[row * S4W + kk * 8 + tg];
                a[i][1] = Ap[(row + 8) * S4W + kk * 8 + tg];
                a[i][2] = Ap[row * S4W + kk * 8 + tg + 4];
                a[i][3] = Ap[(row + 8) * S4W + kk * 8 + tg + 4];
            }
#pragma unroll
            for (int j = 0; j < 8; j++) {
                int n = wc * 64 + j * 8 + g;
                b[j][0] = Bp[n * S4W + kk * 8 + tg];
                b[j][1] = Bp[n * S4W + kk * 8 + tg + 4];
            }
#pragma unroll
            for (int i = 0; i < 2; i++)
#pragma unroll
                for (int j = 0; j < 8; j++)
                    mma_bf16(c[i][j], a[i], b[j]);
        }
        __syncthreads();
    }

#pragma unroll
    for (int i = 0; i < 2; i++)
#pragma unroll
        for (int half = 0; half < 2; half++) {
            size_t grow = m0 + wr * 32 + i * 16 + g + half * 8;
            float* dstf = outv + (size_t)g_asyrow[grow] * C_DIM;
#pragma unroll
            for (int j = 0; j < 8; j++) {
                int colg = wc * 64 + j * 8 + tg * 2;
                float v0 = c[i][j][half * 2]     + __ldg(&bias[colg]);
                float v1 = c[i][j][half * 2 + 1] + __ldg(&bias[colg + 1]);
                v0 = g_y[grow * C_DIM + colg]     + __ldg(&evec[colg]) * v0;
                v1 = g_y[grow * C_DIM + colg + 1] + __ldg(&evec[colg + 1]) * v1;
                *reinterpret_cast<float2*>(dstf + colg) = make_float2(v0, v1);
            }
        }
}

// ---------------------------------------------------------------------------
// attnproj: per-partition attention (register-resident P) + proj GEMM fused.
// SMEM (words): qw 64x196 | otw 64x68 | bW 2x(128x20) | vtw 4x32x36 | kfl 64
// ---------------------------------------------------------------------------
#define QW4 196
#define SAW 68
#define SBW 20
#define BSTG (128 * SBW)
#define AP_Q_OFF  0
#define AP_O_OFF  (64 * QW4)
#define AP_B_OFF  (AP_O_OFF + 64 * SAW)
#define AP_VT_OFF (AP_B_OFF + 2 * BSTG)
#define AP_KFL_OFF (AP_VT_OFF + 4 * 32 * 36)
#define AP_SMEM_BYTES ((AP_KFL_OFF + 64) * 4)

__global__ void __launch_bounds__(256) attnproj_kernel(
    const __nv_bfloat16* __restrict__ gqkv, const __nv_bfloat16* __restrict__ WprojT,
    const float* __restrict__ projb, const float* __restrict__ g1,
    float* __restrict__ outv)
{
    extern __shared__ uint32_t smu[];
    uint32_t* qw  = smu + AP_Q_OFF;
    uint32_t* otw = smu + AP_O_OFF;
    uint32_t* bW  = smu + AP_B_OFF;
    uint32_t* vtw = smu + AP_VT_OFF;
    int* kfl = (int*)(smu + AP_KFL_OFF);

    int m   = blockIdx.x;
    int tid = threadIdx.x;
    int lane = tid & 31;
    int wid  = tid >> 5;
    int g    = lane >> 2;
    int tg   = lane & 3;

    uint32_t q_u = smem_u32(qw);
    uint32_t b_u = smem_u32(bW);

    if (tid < 64) kfl[tid] = g_mflag[m * 64 + tid];

    // stage qkv tile
    for (int i = tid; i < 3072; i += 256) {
        int r = i / 48, t = i - r * 48;
        cp_async16(q_u + (uint32_t)(r * (QW4 * 4) + t * 16),
                   gqkv + (size_t)m * 24576 + r * 384 + t * 8);
    }
    asm volatile("cp.async.commit_group;" ::: "memory");

    auto loadPB = [&](int kc, int s) {
#pragma unroll
        for (int t = 0; t < 2; t++) {
            int idx = tid + t * 256;
            int r = idx >> 2, cc = idx & 3;
            cp_async16(b_u + (uint32_t)(s * (BSTG * 4) + r * (SBW * 4) + cc * 16),
                       WprojT + (size_t)r * C_DIM + kc * 32 + cc * 8);
        }
        asm volatile("cp.async.commit_group;" ::: "memory");
    };
    loadPB(0, 0);                                   // prefetch proj B chunk 0
    asm volatile("cp.async.wait_group 1;" ::: "memory");   // qkv tile ready
    __syncthreads();

    // build VT[h][d][key]
    {
        const __nv_bfloat16* qb = reinterpret_cast<const __nv_bfloat16*>(qw);
        __nv_bfloat16* vtb = reinterpret_cast<__nv_bfloat16*>(vtw);
        for (int i = tid; i < 8192; i += 256) {
            int key = i >> 7, d = i & 127;
            int h = d >> 5, dd = d & 31;
            vtb[h * 2304 + dd * 72 + key] = qb[key * 392 + h * 96 + 64 + dd];
        }
    }
    __syncthreads();

    // ---- attention (register-resident P) ----
    int h = wid >> 1;
    int rbase = (wid & 1) * 32;
    int qh = h * 48, kh = h * 48 + 16;
    const uint32_t* vth = vtw + h * (32 * 36);
    const float scale = 0.17677669529663687f;

    float c[2][8][4];
#pragma unroll
    for (int i = 0; i < 2; i++)
#pragma unroll
        for (int j = 0; j < 8; j++)
#pragma unroll
            for (int q = 0; q < 4; q++) c[i][j][q] = 0.0f;

#pragma unroll
    for (int kq = 0; kq < 2; kq++) {
        uint32_t a[2][4], b[8][2];
#pragma unroll
        for (int i = 0; i < 2; i++) {
            int row = rbase + i * 16 + g;
            a[i][0] = qw[row * QW4 + qh + kq * 8 + tg];
            a[i][1] = qw[(row + 8) * QW4 + qh + kq * 8 + tg];
            a[i][2] = qw[row * QW4 + qh + kq * 8 + tg + 4];
            a[i][3] = qw[(row + 8) * QW4 + qh + kq * 8 + tg + 4];
        }
#pragma unroll
        for (int j = 0; j < 8; j++) {
            int n = j * 8 + g;
            b[j][0] = qw[n * QW4 + kh + kq * 8 + tg];
            b[j][1] = qw[n * QW4 + kh + kq * 8 + tg + 4];
        }
#pragma unroll
        for (int i = 0; i < 2; i++)
#pragma unroll
            for (int j = 0; j < 8; j++)
                mma_bf16(c[i][j], a[i], b[j]);
    }

    unsigned mask = 0;
#pragma unroll
    for (int j = 0; j < 8; j++)
#pragma unroll
        for (int q = 0; q < 2; q++)
            if (kfl[j * 8 + 2 * tg + q] == 2) mask |= 1u << (j * 2 + q);

#pragma unroll
    for (int i = 0; i < 2; i++)
#pragma unroll
        for (int sel = 0; sel < 2; sel++) {
            float mx = -1e30f;
#pragma unroll
            for (int j = 0; j < 8; j++)
#pragma unroll
                for (int q = 0; q < 2; q++) {
                    float v = c[i][j][sel * 2 + q] * scale;
                    if (mask & (1u << (j * 2 + q))) v = -10000.0f;
                    c[i][j][sel * 2 + q] = v;
                    mx = fmaxf(mx, v);
                }
            mx = fmaxf(mx, __shfl_xor_sync(0xffffffffu, mx, 1));
            mx = fmaxf(mx, __shfl_xor_sync(0xffffffffu, mx, 2));
            float s = 0.0f;
#pragma unroll
            for (int j = 0; j < 8; j++)
#pragma unroll
                for (int q = 0; q < 2; q++) {
                    float e = __expf(c[i][j][sel * 2 + q] - mx);
                    c[i][j][sel * 2 + q] = e;
                    s += e;
                }
            s += __shfl_xor_sync(0xffffffffu, s, 1);
            s += __shfl_xor_sync(0xffffffffu, s, 2);
            float rinv = 1.0f / s;
#pragma unroll
            for (int j = 0; j < 8; j++)
#pragma unroll
                for (int q = 0; q < 2; q++)
                    c[i][j][sel * 2 + q] *= rinv;
        }

    float o[2][4][4];
#pragma unroll
    for (int i = 0; i < 2; i++)
#pragma unroll
        for (int j = 0; j < 4; j++)
#pragma unroll
            for (int q = 0; q < 4; q++) o[i][j][q] = 0.0f;

#pragma unroll
    for (int kp = 0; kp < 4; kp++) {
        uint32_t b[4][2];
#pragma unroll
        for (int j = 0; j < 4; j++) {
            int n = j * 8 + g;
            b[j][0] = vth[n * 36 + kp * 8 + tg];
            b[j][1] = vth[n * 36 + kp * 8 + tg + 4];
        }
#pragma unroll
        for (int i = 0; i < 2; i++) {
            uint32_t a[4];
            a[0] = packbf(c[i][2 * kp][0],     c[i][2 * kp][1]);
            a[1] = packbf(c[i][2 * kp][2],     c[i][2 * kp][3]);
            a[2] = packbf(c[i][2 * kp + 1][0], c[i][2 * kp + 1][1]);
            a[3] = packbf(c[i][2 * kp + 1][2], c[i][2 * kp + 1][3]);
#pragma unroll
            for (int j = 0; j < 4; j++)
                mma_bf16(o[i][j], a, b[j]);
        }
    }

    // write O into otw (bf16, stride SAW)
#pragma unroll
    for (int i = 0; i < 2; i++)
#pragma unroll
        for (int j = 0; j < 4; j++) {
            int row = rbase + i * 16 + g;
            int wrd = h * 16 + j * 4 + tg;
            otw[row * SAW + wrd]       = packbf(o[i][j][0], o[i][j][1]);
            otw[(row + 8) * SAW + wrd] = packbf(o[i][j][2], o[i][j][3]);
        }
    __syncthreads();

    // ---- proj GEMM: 64 rows x 128 cols, warp layout 2x4, warp tile 32x32 ----
    {
        int wr2 = wid >> 2;      // 0..1
        int wc2 = wid & 3;       // 0..3
        float pc[2][4][4];
#pragma unroll
        for (int i = 0; i < 2; i++)
#pragma unroll
            for (int j = 0; j < 4; j++)
#pragma unroll
                for (int q = 0; q < 4; q++) pc[i][j][q] = 0.0f;

#pragma unroll
        for (int kc = 0; kc < 4; kc++) {
            int s = kc & 1;
            if (kc < 3) {
                loadPB(kc + 1, s ^ 1);
                asm volatile("cp.async.wait_group 1;" ::: "memory");
            } else {
                asm volatile("cp.async.wait_group 0;" ::: "memory");
            }
            __syncthreads();
            const uint32_t* Bp = bW + s * BSTG;
#pragma unroll
            for (int kk = 0; kk < 2; kk++) {
                int kw = kc * 16 + kk * 8 + tg;
                uint32_t a[2][4], b[4][2];
#pragma unroll
                for (int i = 0; i < 2; i++) {
                    int row = wr2 * 32 + i * 16 + g;
                    a[i][0] = otw[row * SAW + kw];
                    a[i][1] = otw[(row + 8) * SAW + kw];
                    a[i][2] = otw[row * SAW + kw + 4];
                    a[i][3] = otw[(row + 8) * SAW + kw + 4];
                }
#pragma unroll
                for (int j = 0; j < 4; j++) {
                    int n = wc2 * 32 + j * 8 + g;
                    b[j][0] = Bp[n * SBW + kk * 8 + tg];
                    b[j][1] = Bp[n * SBW + kk * 8 + tg + 4];
                }
#pragma unroll
                for (int i = 0; i < 2; i++)
#pragma unroll
                    for (int j = 0; j < 4; j++)
                        mma_bf16(pc[i][j], a[i], b[j]);
            }
            __syncthreads();
        }

#pragma unroll
        for (int i = 0; i < 2; i++)
#pragma unroll
            for (int half = 0; half < 2; half++) {
                int lrow = wr2 * 32 + i * 16 + g + half * 8;
                size_t grow = (size_t)m * 64 + lrow;
                int f = kfl[lrow];
                if (f == 2) continue;
                if (f == 1) {
                    size_t rank = (size_t)g_mrank[grow];
#pragma unroll
                    for (int j = 0; j < 4; j++) {
                        int colg = wc2 * 32 + j * 8 + tg * 2;
                        float v0 = pc[i][j][half * 2]     + __ldg(&projb[colg]);
                        float v1 = pc[i][j][half * 2 + 1] + __ldg(&projb[colg + 1]);
                        v0 = g_xa[rank * C_DIM + colg]     + __ldg(&g1[colg]) * v0;
                        v1 = g_xa[rank * C_DIM + colg + 1] + __ldg(&g1[colg + 1]) * v1;
                        *reinterpret_cast<float2*>(g_y + rank * C_DIM + colg) =
                            make_float2(v0, v1);
                    }
                } else {
                    float* dstf = outv + (size_t)g_mrow[grow] * C_DIM;
#pragma unroll
                    for (int j = 0; j < 4; j++) {
                        int colg = wc2 * 32 + j * 8 + tg * 2;
                        float v0 = pc[i][j][half * 2]     + __ldg(&projb[colg]);
                        float v1 = pc[i][j][half * 2 + 1] + __ldg(&projb[colg + 1]);
                        *reinterpret_cast<float2*>(dstf + colg) = make_float2(v0, v1);
                    }
                }
            }
    }
}

// ---------------------------------------------------------------------------
extern "C" void kernel_launch(void* const* d_in, const int* in_sizes, int n_in,
                              void* d_out, int out_size)
{
    int base = 7;
    if (n_in == 19) base = 5;

    const float* x      = (const float*)d_in[0];
    const int*   iw     = (const int*)d_in[1];
    const int*   ipart  = (const int*)d_in[2];
    const int*   asy    = (const int*)d_in[3];
    const int*   blk    = (const int*)d_in[4];
    const float* ln1w   = (const float*)d_in[base + 0];
    const float* ln1b   = (const float*)d_in[base + 1];
    const float* qkvw   = (const float*)d_in[base + 2];
    const float* qkvb   = (const float*)d_in[base + 3];
    const float* projw  = (const float*)d_in[base + 4];
    const float* projb  = (const float*)d_in[base + 5];
    const float* g1     = (const float*)d_in[base + 6];
    const float* ln2w   = (const float*)d_in[base + 7];
    const float* ln2b   = (const float*)d_in[base + 8];
    const float* w1     = (const float*)d_in[base + 9];
    const float* b1     = (const float*)d_in[base + 10];
    const float* w2     = (const float*)d_in[base + 11];
    const float* b2     = (const float*)d_in[base + 12];
    const float* g2     = (const float*)d_in[base + 13];
    float* out = (float*)d_out;

    __nv_bfloat16 *p_xp, *p_qkv, *p_h;
    __nv_bfloat16 *p_wqkvT, *p_wprojT, *p_w1T, *p_w2T;
    cudaGetSymbolAddress((void**)&p_xp, g_xp_bf);
    cudaGetSymbolAddress((void**)&p_qkv, g_qkv_bf);
    cudaGetSymbolAddress((void**)&p_h, g_h_bf);
    cudaGetSymbolAddress((void**)&p_wqkvT, g_wqkvT);
    cudaGetSymbolAddress((void**)&p_wprojT, g_wprojT);
    cudaGetSymbolAddress((void**)&p_w1T, g_w1T);
    cudaGetSymbolAddress((void**)&p_w2T, g_w2T);

    cudaFuncSetAttribute(gemm5b_kernel<384, 0, 0>,
                         cudaFuncAttributeMaxDynamicSharedMemorySize, GEMM5B_SMEM_BYTES);
    cudaFuncSetAttribute(gemm5b_kernel<512, 2, 1>,
                         cudaFuncAttributeMaxDynamicSharedMemorySize, GEMM5B_SMEM_BYTES);
    cudaFuncSetAttribute(gemm4b_kernel<512, 3>,
                         cudaFuncAttributeMaxDynamicSharedMemorySize, GEMM4B_SMEM_BYTES);
    cudaFuncSetAttribute(attnproj_kernel,
                         cudaFuncAttributeMaxDynamicSharedMemorySize, AP_SMEM_BYTES);

    // 0-2. init + maps + meta + merged weight transpose
    zero_misc_kernel<<<(MW_CNT / 16 + N_WIN / 4 + 255) / 256, 256>>>();
    set_maps_kernel<<<MW_CNT / 256, 256>>>(asy, blk, iw, ipart);
    meta_kernel<<<MW_CNT / 256, 256>>>(ipart, iw);
    wtrans_all_kernel<<<768, 256>>>(qkvw, projw, w1, w2,
                                    p_wqkvT, p_wprojT, p_w1T, p_w2T);
    // 3. fused LN + double-LN + scatter
    ln_kernel<<<N_TOK / 16, 256>>>(x, ln1w, ln1b, out);
    // 4. QKV GEMM
    gemm5b_kernel<384, 0, 0><<<MW_CNT / 128, 256, GEMM5B_SMEM_BYTES>>>(
        p_xp, p_wqkvT, qkvb, p_qkv, nullptr, nullptr);
    // 5. attention + proj fused (per partition)
    attnproj_kernel<<<M_PART, 256, AP_SMEM_BYTES>>>(
        p_qkv, p_wprojT, projb, g1, out);
    // 6. MLP GEMM1 (LN2 fused) + gelu
    gemm5b_kernel<512, 2, 1><<<A_CNT / 128, 256, GEMM5B_SMEM_BYTES>>>(
        nullptr, p_w1T, b1, p_h, ln2w, ln2b);
    // 7. MLP GEMM2 + residual + scatter
    gemm4b_kernel<512, 3><<<A_CNT / 128, 256, GEMM4B_SMEM_BYTES>>>(
        p_h, p_w2T, b2, out, g2);
}

// round 13
// speedup vs baseline: 1.2732x; 1.1167x over previous
#include <cuda_runtime.h>
#include <cuda_bf16.h>
#include <math.h>
#include <stdint.h>

// Problem constants
#define N_TOK   524288
#define N_WIN   8192
#define P_TOK   64
#define C_DIM   128
#define M_PART  4096
#define MW_CNT  262144
#define A_CNT   131072
#define BL_CNT  65536
#define EPS_LN  1e-6f

// ---------------------------------------------------------------------------
// Scratch (device globals — allocation-free rule)
// ---------------------------------------------------------------------------
__device__ float g_xa[(size_t)A_CNT * C_DIM];
__device__ float g_y[(size_t)A_CNT * C_DIM];
__device__ __nv_bfloat16 g_xp_bf[(size_t)MW_CNT * C_DIM];
__device__ __nv_bfloat16 g_wqkvT[384 * 128];
__device__ __nv_bfloat16 g_wprojT[128 * 128];
__device__ __nv_bfloat16 g_w1T[512 * 128];
__device__ __nv_bfloat16 g_w2T[128 * 512];
__device__ unsigned char g_flag[MW_CNT];
__device__ int g_rank[MW_CNT];
__device__ int g_ipos[MW_CNT];
__device__ int g_winv[N_WIN];
__device__ int g_asyrow[A_CNT];
__device__ unsigned char g_mflag[MW_CNT];
__device__ int g_mrow[MW_CNT];
__device__ int g_mrank[MW_CNT];

// ---------------------------------------------------------------------------
// helpers
// ---------------------------------------------------------------------------
__device__ __forceinline__ void mma_bf16(float c[4], const uint32_t a[4], const uint32_t b[2]) {
    asm volatile(
        "mma.sync.aligned.m16n8k16.row.col.f32.bf16.bf16.f32 "
        "{%0,%1,%2,%3}, {%4,%5,%6,%7}, {%8,%9}, {%0,%1,%2,%3};"
        : "+f"(c[0]), "+f"(c[1]), "+f"(c[2]), "+f"(c[3])
        : "r"(a[0]), "r"(a[1]), "r"(a[2]), "r"(a[3]), "r"(b[0]), "r"(b[1]));
}
__device__ __forceinline__ uint32_t smem_u32(const void* p) {
    uint32_t a;
    asm("{ .reg .u64 t; cvta.to.shared.u64 t, %1; cvt.u32.u64 %0, t; }" : "=r"(a) : "l"(p));
    return a;
}
__device__ __forceinline__ void cp_async16(uint32_t dst, const void* src) {
    asm volatile("cp.async.cg.shared.global [%0], [%1], 16;" :: "r"(dst), "l"(src) : "memory");
}
__device__ __forceinline__ uint32_t packbf(float a, float b) {
    __nv_bfloat162 p = __floats2bfloat162_rn(a, b);
    return *reinterpret_cast<uint32_t*>(&p);
}
__device__ __forceinline__ void warp_sum2(float& s1, float& s2) {
#pragma unroll
    for (int o = 16; o; o >>= 1) {
        s1 += __shfl_xor_sync(0xffffffffu, s1, o);
        s2 += __shfl_xor_sync(0xffffffffu, s2, o);
    }
}
__device__ __forceinline__ void warp_sum4(float& a1, float& a2, float& b1, float& b2) {
#pragma unroll
    for (int o = 16; o; o >>= 1) {
        a1 += __shfl_xor_sync(0xffffffffu, a1, o);
        a2 += __shfl_xor_sync(0xffffffffu, a2, o);
        b1 += __shfl_xor_sync(0xffffffffu, b1, o);
        b2 += __shfl_xor_sync(0xffffffffu, b2, o);
    }
}

// ---------------------------------------------------------------------------
// K0/K1/K2: init, maps, meta
// ---------------------------------------------------------------------------
__global__ void __launch_bounds__(256) zero_misc_kernel()
{
    int t = blockIdx.x * 256 + threadIdx.x;
    if (t < MW_CNT / 16)
        reinterpret_cast<uint4*>(g_flag)[t] = make_uint4(0u, 0u, 0u, 0u);
    int u = t - MW_CNT / 16;
    if (u >= 0 && u < N_WIN / 4)
        reinterpret_cast<int4*>(g_winv)[u] = make_int4(-1, -1, -1, -1);
}
__global__ void __launch_bounds__(256) set_maps_kernel(
    const int* __restrict__ asy, const int* __restrict__ blk,
    const int* __restrict__ iw, const int* __restrict__ ipart)
{
    int t = blockIdx.x * 256 + threadIdx.x;
    if (t < MW_CNT) g_ipos[ipart[t]] = t;
    if (t < A_CNT) {
        int g = asy[t];
        g_flag[g] = 1;
        g_rank[g] = t;
        g_asyrow[t] = iw[g >> 6] * 64 + (g & 63);
    } else if (t < A_CNT + BL_CNT) {
        g_flag[blk[t - A_CNT]] = 2;
    }
    if (t < M_PART) g_winv[iw[t]] = t;
}
__global__ void __launch_bounds__(256) meta_kernel(
    const int* __restrict__ ipart, const int* __restrict__ iw)
{
    int i = blockIdx.x * 256 + threadIdx.x;
    if (i >= MW_CNT) return;
    int g = ipart[i];
    int f = g_flag[g];
    g_mflag[i] = (unsigned char)f;
    g_mrow[i]  = iw[g >> 6] * 64 + (g & 63);
    g_mrank[i] = (f == 1) ? g_rank[g] : 0;
}

// ---------------------------------------------------------------------------
// K2b: ALL weight transposes in one launch
// ---------------------------------------------------------------------------
__global__ void __launch_bounds__(256) wtrans_all_kernel(
    const float* __restrict__ qkvw, const float* __restrict__ projw,
    const float* __restrict__ w1, const float* __restrict__ w2,
    __nv_bfloat16* __restrict__ oq, __nv_bfloat16* __restrict__ op,
    __nv_bfloat16* __restrict__ o1, __nv_bfloat16* __restrict__ o2)
{
    int idx = blockIdx.x * 256 + threadIdx.x;
    const float* W; __nv_bfloat16* WT; int K, N, local;
    if (idx < 49152)       { W = qkvw;  WT = oq; K = 128; N = 384; local = idx; }
    else if (idx < 65536)  { W = projw; WT = op; K = 128; N = 128; local = idx - 49152; }
    else if (idx < 131072) { W = w1;    WT = o1; K = 128; N = 512; local = idx - 65536; }
    else                   { W = w2;    WT = o2; K = 512; N = 128; local = idx - 131072; }
    int k = local / N, n = local - k * N;
    WT[n * K + k] = __float2bfloat16(W[(size_t)k * N + n]);
}

// ---------------------------------------------------------------------------
// K3: fused LN + scatter (unchanged)
// ---------------------------------------------------------------------------
__global__ void __launch_bounds__(256) ln_kernel(
    const float* __restrict__ x, const float* __restrict__ w,
    const float* __restrict__ b, float* __restrict__ out)
{
    int wglob = blockIdx.x * 8 + (threadIdx.x >> 5);
    int lane  = threadIdx.x & 31;
    int r0 = wglob * 2;
    int r1 = r0 + 1;

    float4 v0 = reinterpret_cast<const float4*>(x + (size_t)r0 * C_DIM)[lane];
    float4 v1 = reinterpret_cast<const float4*>(x + (size_t)r1 * C_DIM)[lane];
    float4 wv = reinterpret_cast<const float4*>(w)[lane];
    float4 bv = reinterpret_cast<const float4*>(b)[lane];

    float a1 = v0.x + v0.y + v0.z + v0.w;
    float a2 = v0.x*v0.x + v0.y*v0.y + v0.z*v0.z + v0.w*v0.w;
    float c1 = v1.x + v1.y + v1.z + v1.w;
    float c2 = v1.x*v1.x + v1.y*v1.y + v1.z*v1.z + v1.w*v1.w;
    warp_sum4(a1, a2, c1, c2);

#pragma unroll
    for (int rr = 0; rr < 2; rr++) {
        int row = rr ? r1 : r0;
        float4 v = rr ? v1 : v0;
        float s1 = rr ? c1 : a1;
        float s2 = rr ? c2 : a2;
        float m = s1 * (1.0f / C_DIM);
        float var = s2 * (1.0f / C_DIM) - m * m;
        float inv = rsqrtf(var + EPS_LN);
        float4 r;
        r.x = (v.x - m) * inv * wv.x + bv.x; r.y = (v.y - m) * inv * wv.y + bv.y;
        r.z = (v.z - m) * inv * wv.z + bv.z; r.w = (v.w - m) * inv * wv.w + bv.w;

        int n = row >> 6, p = row & 63;
        int widx = g_winv[n];
        if (widx < 0) {
            reinterpret_cast<float4*>(out + (size_t)row * C_DIM)[lane] = r;
        } else {
            int g = widx * 64 + p;
            int f = g_flag[g];
            int ipos = g_ipos[g];
            float4 val = r;
            if (f == 2) {
                reinterpret_cast<float4*>(out + (size_t)row * C_DIM)[lane] = r;
            } else if (f == 1) {
                float t1 = r.x + r.y + r.z + r.w;
                float t2 = r.x*r.x + r.y*r.y + r.z*r.z + r.w*r.w;
                warp_sum2(t1, t2);
                float m2 = t1 * (1.0f / C_DIM);
                float var2 = t2 * (1.0f / C_DIM) - m2 * m2;
                float inv2 = rsqrtf(var2 + EPS_LN);
                val.x = (r.x - m2) * inv2 * wv.x + bv.x;
                val.y = (r.y - m2) * inv2 * wv.y + bv.y;
                val.z = (r.z - m2) * inv2 * wv.z + bv.z;
                val.w = (r.w - m2) * inv2 * wv.w + bv.w;
                reinterpret_cast<float4*>(g_xa + (size_t)g_rank[g] * C_DIM)[lane] = val;
            }
            uint2 u;
            u.x = packbf(val.x, val.y);
            u.y = packbf(val.z, val.w);
            *reinterpret_cast<uint2*>(g_xp_bf + (size_t)ipos * C_DIM + lane * 4) = u;
        }
    }
}

// ---------------------------------------------------------------------------
// qap: QKV GEMM -> attention -> proj GEMM fused, one block per partition.
// SMEM (words): qw 64x196 | xpw 64x68 (xp panel, later O) | bW 2x(128x20) |
//               vtw 4x32x36 | kfl 64      total 26688 words = 106.75 KB
// ---------------------------------------------------------------------------
#define QW4 196
#define SAW 68
#define SBW 20
#define BSTG (128 * SBW)
#define QP_Q_OFF   0
#define QP_XP_OFF  (64 * QW4)
#define QP_B_OFF   (QP_XP_OFF + 64 * SAW)
#define QP_VT_OFF  (QP_B_OFF + 2 * BSTG)
#define QP_KFL_OFF (QP_VT_OFF + 4 * 32 * 36)
#define QP_SMEM_BYTES ((QP_KFL_OFF + 64) * 4)

__global__ void __launch_bounds__(256) qap_kernel(
    const __nv_bfloat16* __restrict__ Ab, const __nv_bfloat16* __restrict__ WqkvT,
    const float* __restrict__ qkvb,
    const __nv_bfloat16* __restrict__ WprojT, const float* __restrict__ projb,
    const float* __restrict__ g1, float* __restrict__ outv)
{
    extern __shared__ uint32_t smu[];
    uint32_t* qw  = smu + QP_Q_OFF;
    uint32_t* xpw = smu + QP_XP_OFF;
    uint32_t* bW  = smu + QP_B_OFF;
    uint32_t* vtw = smu + QP_VT_OFF;
    int* kfl = (int*)(smu + QP_KFL_OFF);

    int m   = blockIdx.x;
    int tid = threadIdx.x;
    int lane = tid & 31;
    int wid  = tid >> 5;
    int g    = lane >> 2;
    int tg   = lane & 3;
    int wr2  = wid >> 2;     // 0..1
    int wc2  = wid & 3;      // 0..3
    size_t r0 = (size_t)m * 64;

    uint32_t xp_u = smem_u32(xpw);
    uint32_t b_u  = smem_u32(bW);

    if (tid < 64) kfl[tid] = g_mflag[r0 + tid];

    // xp panel: 64 rows x 256B = 1024 16B txns
#pragma unroll
    for (int t = 0; t < 4; t++) {
        int idx = tid + t * 256;
        int r = idx >> 4, cc = idx & 15;
        cp_async16(xp_u + (uint32_t)(r * (SAW * 4) + cc * 16),
                   Ab + (r0 + r) * C_DIM + cc * 8);
    }
    auto loadQB = [&](int nc, int kc, int s) {
#pragma unroll
        for (int t = 0; t < 2; t++) {
            int idx = tid + t * 256;
            int r = idx >> 2, cc = idx & 3;
            cp_async16(b_u + (uint32_t)(s * (BSTG * 4) + r * (SBW * 4) + cc * 16),
                       WqkvT + (size_t)(nc * 128 + r) * C_DIM + kc * 32 + cc * 8);
        }
        asm volatile("cp.async.commit_group;" ::: "memory");
    };
    auto loadPB = [&](int kc, int s) {
#pragma unroll
        for (int t = 0; t < 2; t++) {
            int idx = tid + t * 256;
            int r = idx >> 2, cc = idx & 3;
            cp_async16(b_u + (uint32_t)(s * (BSTG * 4) + r * (SBW * 4) + cc * 16),
                       WprojT + (size_t)r * C_DIM + kc * 32 + cc * 8);
        }
        asm volatile("cp.async.commit_group;" ::: "memory");
    };

    loadQB(0, 0, 0);   // group includes xp panel txns

    // ---- Phase 1: QKV GEMM, 3 n-chunks, warp tile 32x32 ----
#pragma unroll 1
    for (int nc = 0; nc < 3; nc++) {
        if (nc > 0) loadQB(nc, 0, 0);
        float pc[2][4][4];
#pragma unroll
        for (int i = 0; i < 2; i++)
#pragma unroll
            for (int j = 0; j < 4; j++)
#pragma unroll
                for (int q = 0; q < 4; q++) pc[i][j][q] = 0.0f;

#pragma unroll
        for (int kc = 0; kc < 4; kc++) {
            int s = kc & 1;
            if (kc < 3) {
                loadQB(nc, kc + 1, s ^ 1);
                asm volatile("cp.async.wait_group 1;" ::: "memory");
            } else {
                asm volatile("cp.async.wait_group 0;" ::: "memory");
            }
            __syncthreads();
            const uint32_t* Bp = bW + s * BSTG;
#pragma unroll
            for (int kk = 0; kk < 2; kk++) {
                int kw = kc * 16 + kk * 8 + tg;
                uint32_t a[2][4], b[4][2];
#pragma unroll
                for (int i = 0; i < 2; i++) {
                    int row = wr2 * 32 + i * 16 + g;
                    a[i][0] = xpw[row * SAW + kw];
                    a[i][1] = xpw[(row + 8) * SAW + kw];
                    a[i][2] = xpw[row * SAW + kw + 4];
                    a[i][3] = xpw[(row + 8) * SAW + kw + 4];
                }
#pragma unroll
                for (int j = 0; j < 4; j++) {
                    int n = wc2 * 32 + j * 8 + g;
                    b[j][0] = Bp[n * SBW + kk * 8 + tg];
                    b[j][1] = Bp[n * SBW + kk * 8 + tg + 4];
                }
#pragma unroll
                for (int i = 0; i < 2; i++)
#pragma unroll
                    for (int j = 0; j < 4; j++)
                        mma_bf16(pc[i][j], a[i], b[j]);
            }
            __syncthreads();
        }
        // epilogue -> qw (bf16)
#pragma unroll
        for (int i = 0; i < 2; i++)
#pragma unroll
            for (int half = 0; half < 2; half++) {
                int row = wr2 * 32 + i * 16 + g + half * 8;
#pragma unroll
                for (int j = 0; j < 4; j++) {
                    int colg = nc * 128 + wc2 * 32 + j * 8 + tg * 2;
                    float v0 = pc[i][j][half * 2]     + __ldg(&qkvb[colg]);
                    float v1 = pc[i][j][half * 2 + 1] + __ldg(&qkvb[colg + 1]);
                    qw[row * QW4 + (colg >> 1)] = packbf(v0, v1);
                }
            }
    }
    __syncthreads();

    loadPB(0, 0);   // prefetch proj B chunk 0 (covers VT build + attention)

    // ---- Phase 2: build VT[h][d][key] ----
    {
        const __nv_bfloat16* qb = reinterpret_cast<const __nv_bfloat16*>(qw);
        __nv_bfloat16* vtb = reinterpret_cast<__nv_bfloat16*>(vtw);
        for (int i = tid; i < 8192; i += 256) {
            int key = i >> 7, d = i & 127;
            int h = d >> 5, dd = d & 31;
            vtb[h * 2304 + dd * 72 + key] = qb[key * 392 + h * 96 + 64 + dd];
        }
    }
    __syncthreads();

    // ---- Phase 3: attention (register-resident P) ----
    int h = wid >> 1;
    int rbase = (wid & 1) * 32;
    int qh = h * 48, kh = h * 48 + 16;
    const uint32_t* vth = vtw + h * (32 * 36);
    const float scale = 0.17677669529663687f;

    {
        float c[2][8][4];
#pragma unroll
        for (int i = 0; i < 2; i++)
#pragma unroll
            for (int j = 0; j < 8; j++)
#pragma unroll
                for (int q = 0; q < 4; q++) c[i][j][q] = 0.0f;

#pragma unroll
        for (int kq = 0; kq < 2; kq++) {
            uint32_t a[2][4], b[8][2];
#pragma unroll
            for (int i = 0; i < 2; i++) {
                int row = rbase + i * 16 + g;
                a[i][0] = qw[row * QW4 + qh + kq * 8 + tg];
                a[i][1] = qw[(row + 8) * QW4 + qh + kq * 8 + tg];
                a[i][2] = qw[row * QW4 + qh + kq * 8 + tg + 4];
                a[i][3] = qw[(row + 8) * QW4 + qh + kq * 8 + tg + 4];
            }
#pragma unroll
            for (int j = 0; j < 8; j++) {
                int n = j * 8 + g;
                b[j][0] = qw[n * QW4 + kh + kq * 8 + tg];
                b[j][1] = qw[n * QW4 + kh + kq * 8 + tg + 4];
            }
#pragma unroll
            for (int i = 0; i < 2; i++)
#pragma unroll
                for (int j = 0; j < 8; j++)
                    mma_bf16(c[i][j], a[i], b[j]);
        }

        unsigned mask = 0;
#pragma unroll
        for (int j = 0; j < 8; j++)
#pragma unroll
            for (int q = 0; q < 2; q++)
                if (kfl[j * 8 + 2 * tg + q] == 2) mask |= 1u << (j * 2 + q);

#pragma unroll
        for (int i = 0; i < 2; i++)
#pragma unroll
            for (int sel = 0; sel < 2; sel++) {
                float mx = -1e30f;
#pragma unroll
                for (int j = 0; j < 8; j++)
#pragma unroll
                    for (int q = 0; q < 2; q++) {
                        float v = c[i][j][sel * 2 + q] * scale;
                        if (mask & (1u << (j * 2 + q))) v = -10000.0f;
                        c[i][j][sel * 2 + q] = v;
                        mx = fmaxf(mx, v);
                    }
                mx = fmaxf(mx, __shfl_xor_sync(0xffffffffu, mx, 1));
                mx = fmaxf(mx, __shfl_xor_sync(0xffffffffu, mx, 2));
                float s = 0.0f;
#pragma unroll
                for (int j = 0; j < 8; j++)
#pragma unroll
                    for (int q = 0; q < 2; q++) {
                        float e = __expf(c[i][j][sel * 2 + q] - mx);
                        c[i][j][sel * 2 + q] = e;
                        s += e;
                    }
                s += __shfl_xor_sync(0xffffffffu, s, 1);
                s += __shfl_xor_sync(0xffffffffu, s, 2);
                float rinv = 1.0f / s;
#pragma unroll
                for (int j = 0; j < 8; j++)
#pragma unroll
                    for (int q = 0; q < 2; q++)
                        c[i][j][sel * 2 + q] *= rinv;
            }

        float o[2][4][4];
#pragma unroll
        for (int i = 0; i < 2; i++)
#pragma unroll
            for (int j = 0; j < 4; j++)
#pragma unroll
                for (int q = 0; q < 4; q++) o[i][j][q] = 0.0f;

#pragma unroll
        for (int kp = 0; kp < 4; kp++) {
            uint32_t b[4][2];
#pragma unroll
            for (int j = 0; j < 4; j++) {
                int n = j * 8 + g;
                b[j][0] = vth[n * 36 + kp * 8 + tg];
                b[j][1] = vth[n * 36 + kp * 8 + tg + 4];
            }
#pragma unroll
            for (int i = 0; i < 2; i++) {
                uint32_t a[4];
                a[0] = packbf(c[i][2 * kp][0],     c[i][2 * kp][1]);
                a[1] = packbf(c[i][2 * kp][2],     c[i][2 * kp][3]);
                a[2] = packbf(c[i][2 * kp + 1][0], c[i][2 * kp + 1][1]);
                a[3] = packbf(c[i][2 * kp + 1][2], c[i][2 * kp + 1][3]);
#pragma unroll
                for (int j = 0; j < 4; j++)
                    mma_bf16(o[i][j], a, b[j]);
            }
        }

        // O into xpw (xp panel dead after QKV)
#pragma unroll
        for (int i = 0; i < 2; i++)
#pragma unroll
            for (int j = 0; j < 4; j++) {
                int row = rbase + i * 16 + g;
                int wrd = h * 16 + j * 4 + tg;
                xpw[row * SAW + wrd]       = packbf(o[i][j][0], o[i][j][1]);
                xpw[(row + 8) * SAW + wrd] = packbf(o[i][j][2], o[i][j][3]);
            }
    }
    __syncthreads();

    // ---- Phase 4: proj GEMM (64x128, K=128) + scatter ----
    {
        float pc[2][4][4];
#pragma unroll
        for (int i = 0; i < 2; i++)
#pragma unroll
            for (int j = 0; j < 4; j++)
#pragma unroll
                for (int q = 0; q < 4; q++) pc[i][j][q] = 0.0f;

#pragma unroll
        for (int kc = 0; kc < 4; kc++) {
            int s = kc & 1;
            if (kc < 3) {
                loadPB(kc + 1, s ^ 1);
                asm volatile("cp.async.wait_group 1;" ::: "memory");
            } else {
                asm volatile("cp.async.wait_group 0;" ::: "memory");
            }
            __syncthreads();
            const uint32_t* Bp = bW + s * BSTG;
#pragma unroll
            for (int kk = 0; kk < 2; kk++) {
                int kw = kc * 16 + kk * 8 + tg;
                uint32_t a[2][4], b[4][2];
#pragma unroll
                for (int i = 0; i < 2; i++) {
                    int row = wr2 * 32 + i * 16 + g;
                    a[i][0] = xpw[row * SAW + kw];
                    a[i][1] = xpw[(row + 8) * SAW + kw];
                    a[i][2] = xpw[row * SAW + kw + 4];
                    a[i][3] = xpw[(row + 8) * SAW + kw + 4];
                }
#pragma unroll
                for (int j = 0; j < 4; j++) {
                    int n = wc2 * 32 + j * 8 + g;
                    b[j][0] = Bp[n * SBW + kk * 8 + tg];
                    b[j][1] = Bp[n * SBW + kk * 8 + tg + 4];
                }
#pragma unroll
                for (int i = 0; i < 2; i++)
#pragma unroll
                    for (int j = 0; j < 4; j++)
                        mma_bf16(pc[i][j], a[i], b[j]);
            }
            __syncthreads();
        }

#pragma unroll
        for (int i = 0; i < 2; i++)
#pragma unroll
            for (int half = 0; half < 2; half++) {
                int lrow = wr2 * 32 + i * 16 + g + half * 8;
                size_t grow = r0 + lrow;
                int f = kfl[lrow];
                if (f == 2) continue;
                if (f == 1) {
                    size_t rank = (size_t)g_mrank[grow];
#pragma unroll
                    for (int j = 0; j < 4; j++) {
                        int colg = wc2 * 32 + j * 8 + tg * 2;
                        float v0 = pc[i][j][half * 2]     + __ldg(&projb[colg]);
                        float v1 = pc[i][j][half * 2 + 1] + __ldg(&projb[colg + 1]);
                        v0 = g_xa[rank * C_DIM + colg]     + __ldg(&g1[colg]) * v0;
                        v1 = g_xa[rank * C_DIM + colg + 1] + __ldg(&g1[colg + 1]) * v1;
                        *reinterpret_cast<float2*>(g_y + rank * C_DIM + colg) =
                            make_float2(v0, v1);
                    }
                } else {
                    float* dstf = outv + (size_t)g_mrow[grow] * C_DIM;
#pragma unroll
                    for (int j = 0; j < 4; j++) {
                        int colg = wc2 * 32 + j * 8 + tg * 2;
                        float v0 = pc[i][j][half * 2]     + __ldg(&projb[colg]);
                        float v1 = pc[i][j][half * 2 + 1] + __ldg(&projb[colg + 1]);
                        *reinterpret_cast<float2*>(dstf + colg) = make_float2(v0, v1);
                    }
                }
            }
    }
}

// ---------------------------------------------------------------------------
// mlpf: LN2 -> MLP1(gelu) -> MLP2 + residual scatter, block = 64 asy rows.
// SMEM (words): aw 64x68 | hw 64x260 | bW 2x(128x20)   total 104.4 KB
// ---------------------------------------------------------------------------
#define SHW 260
#define MF_A_OFF 0
#define MF_H_OFF (64 * SAW)
#define MF_B_OFF (MF_H_OFF + 64 * SHW)
#define MF_SMEM_BYTES ((MF_B_OFF + 2 * BSTG) * 4)

__global__ void __launch_bounds__(256) mlpf_kernel(
    const __nv_bfloat16* __restrict__ W1T, const float* __restrict__ b1,
    const __nv_bfloat16* __restrict__ W2T, const float* __restrict__ b2,
    const float* __restrict__ ln2w, const float* __restrict__ ln2b,
    const float* __restrict__ g2, float* __restrict__ outv)
{
    extern __shared__ uint32_t smu[];
    uint32_t* aw = smu + MF_A_OFF;
    uint32_t* hw = smu + MF_H_OFF;
    uint32_t* bW = smu + MF_B_OFF;

    int tid  = threadIdx.x;
    int lane = tid & 31;
    int wid  = tid >> 5;
    int g    = lane >> 2;
    int tg   = lane & 3;
    int wr2  = wid >> 2;
    int wc2  = wid & 3;
    size_t m0 = (size_t)blockIdx.x * 64;

    uint32_t b_u = smem_u32(bW);

    auto loadB1 = [&](int nc, int kc, int s) {
#pragma unroll
        for (int t = 0; t < 2; t++) {
            int idx = tid + t * 256;
            int r = idx >> 2, cc = idx & 3;
            cp_async16(b_u + (uint32_t)(s * (BSTG * 4) + r * (SBW * 4) + cc * 16),
                       W1T + (size_t)(nc * 128 + r) * C_DIM + kc * 32 + cc * 8);
        }
        asm volatile("cp.async.commit_group;" ::: "memory");
    };
    auto loadB2 = [&](int kc, int s) {
#pragma unroll
        for (int t = 0; t < 2; t++) {
            int idx = tid + t * 256;
            int r = idx >> 2, cc = idx & 3;
            cp_async16(b_u + (uint32_t)(s * (BSTG * 4) + r * (SBW * 4) + cc * 16),
                       W2T + (size_t)r * 512 + kc * 32 + cc * 8);
        }
        asm volatile("cp.async.commit_group;" ::: "memory");
    };

    loadB1(0, 0, 0);

    // LN2 over g_y -> bf16 A panel (warp per 8 rows)
    {
        float4 wv = reinterpret_cast<const float4*>(ln2w)[lane];
        float4 bv = reinterpret_cast<const float4*>(ln2b)[lane];
        for (int it = 0; it < 8; it++) {
            int r = wid * 8 + it;
            float4 v = reinterpret_cast<const float4*>(g_y + (m0 + r) * C_DIM)[lane];
            float s1 = v.x + v.y + v.z + v.w;
            float s2 = v.x*v.x + v.y*v.y + v.z*v.z + v.w*v.w;
            warp_sum2(s1, s2);
            float m = s1 * (1.0f / C_DIM);
            float var = s2 * (1.0f / C_DIM) - m * m;
            float inv = rsqrtf(var + EPS_LN);
            aw[r * SAW + lane * 2] = packbf(
                (v.x - m) * inv * wv.x + bv.x, (v.y - m) * inv * wv.y + bv.y);
            aw[r * SAW + lane * 2 + 1] = packbf(
                (v.z - m) * inv * wv.z + bv.z, (v.w - m) * inv * wv.w + bv.w);
        }
    }

    // ---- MLP1: 4 n-chunks of 128, warp tile 32x32, gelu -> hw ----
#pragma unroll 1
    for (int nc = 0; nc < 4; nc++) {
        if (nc > 0) loadB1(nc, 0, 0);
        float pc[2][4][4];
#pragma unroll
        for (int i = 0; i < 2; i++)
#pragma unroll
            for (int j = 0; j < 4; j++)
#pragma unroll
                for (int q = 0; q < 4; q++) pc[i][j][q] = 0.0f;

#pragma unroll
        for (int kc = 0; kc < 4; kc++) {
            int s = kc & 1;
            if (kc < 3) {
                loadB1(nc, kc + 1, s ^ 1);
                asm volatile("cp.async.wait_group 1;" ::: "memory");
            } else {
                asm volatile("cp.async.wait_group 0;" ::: "memory");
            }
            __syncthreads();
            const uint32_t* Bp = bW + s * BSTG;
#pragma unroll
            for (int kk = 0; kk < 2; kk++) {
                int kw = kc * 16 + kk * 8 + tg;
                uint32_t a[2][4], b[4][2];
#pragma unroll
                for (int i = 0; i < 2; i++) {
                    int row = wr2 * 32 + i * 16 + g;
                    a[i][0] = aw[row * SAW + kw];
                    a[i][1] = aw[(row + 8) * SAW + kw];
                    a[i][2] = aw[row * SAW + kw + 4];
                    a[i][3] = aw[(row + 8) * SAW + kw + 4];
                }
#pragma unroll
                for (int j = 0; j < 4; j++) {
                    int n = wc2 * 32 + j * 8 + g;
                    b[j][0] = Bp[n * SBW + kk * 8 + tg];
                    b[j][1] = Bp[n * SBW + kk * 8 + tg + 4];
                }
#pragma unroll
                for (int i = 0; i < 2; i++)
#pragma unroll
                    for (int j = 0; j < 4; j++)
                        mma_bf16(pc[i][j], a[i], b[j]);
            }
            __syncthreads();
        }
#pragma unroll
        for (int i = 0; i < 2; i++)
#pragma unroll
            for (int half = 0; half < 2; half++) {
                int row = wr2 * 32 + i * 16 + g + half * 8;
#pragma unroll
                for (int j = 0; j < 4; j++) {
                    int colg = nc * 128 + wc2 * 32 + j * 8 + tg * 2;
                    float v0 = pc[i][j][half * 2]     + __ldg(&b1[colg]);
                    float v1 = pc[i][j][half * 2 + 1] + __ldg(&b1[colg + 1]);
                    v0 = 0.5f * v0 * (1.0f + erff(v0 * 0.7071067811865476f));
                    v1 = 0.5f * v1 * (1.0f + erff(v1 * 0.7071067811865476f));
                    hw[row * SHW + (colg >> 1)] = packbf(v0, v1);
                }
            }
    }
    __syncthreads();

    loadB2(0, 0);

    // ---- MLP2: 64x128, K=512 (16 k-chunks) + residual scatter ----
    {
        float pc[2][4][4];
#pragma unroll
        for (int i = 0; i < 2; i++)
#pragma unroll
            for (int j = 0; j < 4; j++)
#pragma unroll
                for (int q = 0; q < 4; q++) pc[i][j][q] = 0.0f;

#pragma unroll 1
        for (int kc = 0; kc < 16; kc++) {
            int s = kc & 1;
            if (kc + 1 < 16) {
                loadB2(kc + 1, s ^ 1);
                asm volatile("cp.async.wait_group 1;" ::: "memory");
            } else {
                asm volatile("cp.async.wait_group 0;" ::: "memory");
            }
            __syncthreads();
            const uint32_t* Bp = bW + s * BSTG;
#pragma unroll
            for (int kk = 0; kk < 2; kk++) {
                int kw = kc * 16 + kk * 8 + tg;
                uint32_t a[2][4], b[4][2];
#pragma unroll
                for (int i = 0; i < 2; i++) {
                    int row = wr2 * 32 + i * 16 + g;
                    a[i][0] = hw[row * SHW + kw];
                    a[i][1] = hw[(row + 8) * SHW + kw];
                    a[i][2] = hw[row * SHW + kw + 4];
                    a[i][3] = hw[(row + 8) * SHW + kw + 4];
                }
#pragma unroll
                for (int j = 0; j < 4; j++) {
                    int n = wc2 * 32 + j * 8 + g;
                    b[j][0] = Bp[n * SBW + kk * 8 + tg];
                    b[j][1] = Bp[n * SBW + kk * 8 + tg + 4];
                }
#pragma unroll
                for (int i = 0; i < 2; i++)
#pragma unroll
                    for (int j = 0; j < 4; j++)
                        mma_bf16(pc[i][j], a[i], b[j]);
            }
            __syncthreads();
        }

#pragma unroll
        for (int i = 0; i < 2; i++)
#pragma unroll
            for (int half = 0; half < 2; half++) {
                size_t grow = m0 + wr2 * 32 + i * 16 + g + half * 8;
                float* dstf = outv + (size_t)g_asyrow[grow] * C_DIM;
#pragma unroll
                for (int j = 0; j < 4; j++) {
                    int colg = wc2 * 32 + j * 8 + tg * 2;
                    float v0 = pc[i][j][half * 2]     + __ldg(&b2[colg]);
                    float v1 = pc[i][j][half * 2 + 1] + __ldg(&b2[colg + 1]);
                    v0 = g_y[grow * C_DIM + colg]     + __ldg(&g2[colg]) * v0;
                    v1 = g_y[grow * C_DIM + colg + 1] + __ldg(&g2[colg + 1]) * v1;
                    *reinterpret_cast<float2*>(dstf + colg) = make_float2(v0, v1);
                }
            }
    }
}

// ---------------------------------------------------------------------------
extern "C" void kernel_launch(void* const* d_in, const int* in_sizes, int n_in,
                              void* d_out, int out_size)
{
    int base = 7;
    if (n_in == 19) base = 5;

    const float* x      = (const float*)d_in[0];
    const int*   iw     = (const int*)d_in[1];
    const int*   ipart  = (const int*)d_in[2];
    const int*   asy    = (const int*)d_in[3];
    const int*   blk    = (const int*)d_in[4];
    const float* ln1w   = (const float*)d_in[base + 0];
    const float* ln1b   = (const float*)d_in[base + 1];
    const float* qkvw   = (const float*)d_in[base + 2];
    const float* qkvb   = (const float*)d_in[base + 3];
    const float* projw  = (const float*)d_in[base + 4];
    const float* projb  = (const float*)d_in[base + 5];
    const float* g1     = (const float*)d_in[base + 6];
    const float* ln2w   = (const float*)d_in[base + 7];
    const float* ln2b   = (const float*)d_in[base + 8];
    const float* w1     = (const float*)d_in[base + 9];
    const float* b1     = (const float*)d_in[base + 10];
    const float* w2     = (const float*)d_in[base + 11];
    const float* b2     = (const float*)d_in[base + 12];
    const float* g2     = (const float*)d_in[base + 13];
    float* out = (float*)d_out;

    __nv_bfloat16 *p_xp, *p_wqkvT, *p_wprojT, *p_w1T, *p_w2T;
    cudaGetSymbolAddress((void**)&p_xp, g_xp_bf);
    cudaGetSymbolAddress((void**)&p_wqkvT, g_wqkvT);
    cudaGetSymbolAddress((void**)&p_wprojT, g_wprojT);
    cudaGetSymbolAddress((void**)&p_w1T, g_w1T);
    cudaGetSymbolAddress((void**)&p_w2T, g_w2T);

    cudaFuncSetAttribute(qap_kernel,
                         cudaFuncAttributeMaxDynamicSharedMemorySize, QP_SMEM_BYTES);
    cudaFuncSetAttribute(mlpf_kernel,
                         cudaFuncAttributeMaxDynamicSharedMemorySize, MF_SMEM_BYTES);

    // 0-2. init + maps + meta + merged weight transpose
    zero_misc_kernel<<<(MW_CNT / 16 + N_WIN / 4 + 255) / 256, 256>>>();
    set_maps_kernel<<<MW_CNT / 256, 256>>>(asy, blk, iw, ipart);
    meta_kernel<<<MW_CNT / 256, 256>>>(ipart, iw);
    wtrans_all_kernel<<<768, 256>>>(qkvw, projw, w1, w2,
                                    p_wqkvT, p_wprojT, p_w1T, p_w2T);
    // 3. fused LN + double-LN + scatter
    ln_kernel<<<N_TOK / 16, 256>>>(x, ln1w, ln1b, out);
    // 4. QKV -> attention -> proj fused (per partition)
    qap_kernel<<<M_PART, 256, QP_SMEM_BYTES>>>(
        p_xp, p_wqkvT, qkvb, p_wprojT, projb, g1, out);
    // 5. LN2 -> MLP1 -> MLP2 fused (per 64 asy rows)
    mlpf_kernel<<<A_CNT / 64, 256, MF_SMEM_BYTES>>>(
        p_w1T, b1, p_w2T, b2, ln2w, ln2b, g2, out);
}

// round 15
// speedup vs baseline: 1.3036x; 1.0238x over previous
#include <cuda_runtime.h>
#include <cuda_bf16.h>
#include <math.h>
#include <stdint.h>

// Problem constants
#define N_TOK   524288
#define N_WIN   8192
#define P_TOK   64
#define C_DIM   128
#define M_PART  4096
#define MW_CNT  262144
#define A_CNT   131072
#define BL_CNT  65536
#define EPS_LN  1e-6f

// ---------------------------------------------------------------------------
// Scratch (device globals — allocation-free rule)
// ---------------------------------------------------------------------------
__device__ float g_xa[(size_t)A_CNT * C_DIM];
__device__ float g_y[(size_t)A_CNT * C_DIM];
__device__ __nv_bfloat16 g_xp_bf[(size_t)MW_CNT * C_DIM];
__device__ __nv_bfloat16 g_wqkvT[384 * 128];
__device__ __nv_bfloat16 g_wprojT[128 * 128];
__device__ __nv_bfloat16 g_w1T[512 * 128];
__device__ __nv_bfloat16 g_w2T[128 * 512];
__device__ unsigned char g_flag[MW_CNT];
__device__ int g_rank[MW_CNT];
__device__ int g_ipos[MW_CNT];
__device__ int g_winv[N_WIN];
__device__ int g_asyrow[A_CNT];
__device__ unsigned char g_mflag[MW_CNT];
__device__ int g_mrow[MW_CNT];
__device__ int g_mrank[MW_CNT];

// ---------------------------------------------------------------------------
// helpers
// ---------------------------------------------------------------------------
__device__ __forceinline__ void mma_bf16(float c[4], const uint32_t a[4], const uint32_t b[2]) {
    asm volatile(
        "mma.sync.aligned.m16n8k16.row.col.f32.bf16.bf16.f32 "
        "{%0,%1,%2,%3}, {%4,%5,%6,%7}, {%8,%9}, {%0,%1,%2,%3};"
        : "+f"(c[0]), "+f"(c[1]), "+f"(c[2]), "+f"(c[3])
        : "r"(a[0]), "r"(a[1]), "r"(a[2]), "r"(a[3]), "r"(b[0]), "r"(b[1]));
}
__device__ __forceinline__ uint32_t smem_u32(const void* p) {
    uint32_t a;
    asm("{ .reg .u64 t; cvta.to.shared.u64 t, %1; cvt.u32.u64 %0, t; }" : "=r"(a) : "l"(p));
    return a;
}
__device__ __forceinline__ void cp_async16(uint32_t dst, const void* src) {
    asm volatile("cp.async.cg.shared.global [%0], [%1], 16;" :: "r"(dst), "l"(src) : "memory");
}
__device__ __forceinline__ uint32_t packbf(float a, float b) {
    __nv_bfloat162 p = __floats2bfloat162_rn(a, b);
    return *reinterpret_cast<uint32_t*>(&p);
}
__device__ __forceinline__ void warp_sum2(float& s1, float& s2) {
#pragma unroll
    for (int o = 16; o; o >>= 1) {
        s1 += __shfl_xor_sync(0xffffffffu, s1, o);
        s2 += __shfl_xor_sync(0xffffffffu, s2, o);
    }
}
__device__ __forceinline__ void warp_sum4(float& a1, float& a2, float& b1, float& b2) {
#pragma unroll
    for (int o = 16; o; o >>= 1) {
        a1 += __shfl_xor_sync(0xffffffffu, a1, o);
        a2 += __shfl_xor_sync(0xffffffffu, a2, o);
        b1 += __shfl_xor_sync(0xffffffffu, b1, o);
        b2 += __shfl_xor_sync(0xffffffffu, b2, o);
    }
}

// ---------------------------------------------------------------------------
// K0/K1/K2: init, maps, meta
// ---------------------------------------------------------------------------
__global__ void __launch_bounds__(256) zero_misc_kernel()
{
    int t = blockIdx.x * 256 + threadIdx.x;
    if (t < MW_CNT / 16)
        reinterpret_cast<uint4*>(g_flag)[t] = make_uint4(0u, 0u, 0u, 0u);
    int u = t - MW_CNT / 16;
    if (u >= 0 && u < N_WIN / 4)
        reinterpret_cast<int4*>(g_winv)[u] = make_int4(-1, -1, -1, -1);
}
__global__ void __launch_bounds__(256) set_maps_kernel(
    const int* __restrict__ asy, const int* __restrict__ blk,
    const int* __restrict__ iw, const int* __restrict__ ipart)
{
    int t = blockIdx.x * 256 + threadIdx.x;
    if (t < MW_CNT) g_ipos[ipart[t]] = t;
    if (t < A_CNT) {
        int g = asy[t];
        g_flag[g] = 1;
        g_rank[g] = t;
        g_asyrow[t] = iw[g >> 6] * 64 + (g & 63);
    } else if (t < A_CNT + BL_CNT) {
        g_flag[blk[t - A_CNT]] = 2;
    }
    if (t < M_PART) g_winv[iw[t]] = t;
}
__global__ void __launch_bounds__(256) meta_kernel(
    const int* __restrict__ ipart, const int* __restrict__ iw)
{
    int i = blockIdx.x * 256 + threadIdx.x;
    if (i >= MW_CNT) return;
    int g = ipart[i];
    int f = g_flag[g];
    g_mflag[i] = (unsigned char)f;
    g_mrow[i]  = iw[g >> 6] * 64 + (g & 63);
    g_mrank[i] = (f == 1) ? g_rank[g] : 0;
}

// ---------------------------------------------------------------------------
// K2b: ALL weight transposes in one launch
// ---------------------------------------------------------------------------
__global__ void __launch_bounds__(256) wtrans_all_kernel(
    const float* __restrict__ qkvw, const float* __restrict__ projw,
    const float* __restrict__ w1, const float* __restrict__ w2,
    __nv_bfloat16* __restrict__ oq, __nv_bfloat16* __restrict__ op,
    __nv_bfloat16* __restrict__ o1, __nv_bfloat16* __restrict__ o2)
{
    int idx = blockIdx.x * 256 + threadIdx.x;
    const float* W; __nv_bfloat16* WT; int K, N, local;
    if (idx < 49152)       { W = qkvw;  WT = oq; K = 128; N = 384; local = idx; }
    else if (idx < 65536)  { W = projw; WT = op; K = 128; N = 128; local = idx - 49152; }
    else if (idx < 131072) { W = w1;    WT = o1; K = 128; N = 512; local = idx - 65536; }
    else                   { W = w2;    WT = o2; K = 512; N = 128; local = idx - 131072; }
    int k = local / N, n = local - k * N;
    WT[n * K + k] = __float2bfloat16(W[(size_t)k * N + n]);
}

// ---------------------------------------------------------------------------
// K3: fused LN + scatter (unchanged)
// ---------------------------------------------------------------------------
__global__ void __launch_bounds__(256) ln_kernel(
    const float* __restrict__ x, const float* __restrict__ w,
    const float* __restrict__ b, float* __restrict__ out)
{
    int wglob = blockIdx.x * 8 + (threadIdx.x >> 5);
    int lane  = threadIdx.x & 31;
    int r0 = wglob * 2;
    int r1 = r0 + 1;

    float4 v0 = reinterpret_cast<const float4*>(x + (size_t)r0 * C_DIM)[lane];
    float4 v1 = reinterpret_cast<const float4*>(x + (size_t)r1 * C_DIM)[lane];
    float4 wv = reinterpret_cast<const float4*>(w)[lane];
    float4 bv = reinterpret_cast<const float4*>(b)[lane];

    float a1 = v0.x + v0.y + v0.z + v0.w;
    float a2 = v0.x*v0.x + v0.y*v0.y + v0.z*v0.z + v0.w*v0.w;
    float c1 = v1.x + v1.y + v1.z + v1.w;
    float c2 = v1.x*v1.x + v1.y*v1.y + v1.z*v1.z + v1.w*v1.w;
    warp_sum4(a1, a2, c1, c2);

#pragma unroll
    for (int rr = 0; rr < 2; rr++) {
        int row = rr ? r1 : r0;
        float4 v = rr ? v1 : v0;
        float s1 = rr ? c1 : a1;
        float s2 = rr ? c2 : a2;
        float m = s1 * (1.0f / C_DIM);
        float var = s2 * (1.0f / C_DIM) - m * m;
        float inv = rsqrtf(var + EPS_LN);
        float4 r;
        r.x = (v.x - m) * inv * wv.x + bv.x; r.y = (v.y - m) * inv * wv.y + bv.y;
        r.z = (v.z - m) * inv * wv.z + bv.z; r.w = (v.w - m) * inv * wv.w + bv.w;

        int n = row >> 6, p = row & 63;
        int widx = g_winv[n];
        if (widx < 0) {
            reinterpret_cast<float4*>(out + (size_t)row * C_DIM)[lane] = r;
        } else {
            int g = widx * 64 + p;
            int f = g_flag[g];
            int ipos = g_ipos[g];
            float4 val = r;
            if (f == 2) {
                reinterpret_cast<float4*>(out + (size_t)row * C_DIM)[lane] = r;
            } else if (f == 1) {
                float t1 = r.x + r.y + r.z + r.w;
                float t2 = r.x*r.x + r.y*r.y + r.z*r.z + r.w*r.w;
                warp_sum2(t1, t2);
                float m2 = t1 * (1.0f / C_DIM);
                float var2 = t2 * (1.0f / C_DIM) - m2 * m2;
                float inv2 = rsqrtf(var2 + EPS_LN);
                val.x = (r.x - m2) * inv2 * wv.x + bv.x;
                val.y = (r.y - m2) * inv2 * wv.y + bv.y;
                val.z = (r.z - m2) * inv2 * wv.z + bv.z;
                val.w = (r.w - m2) * inv2 * wv.w + bv.w;
                reinterpret_cast<float4*>(g_xa + (size_t)g_rank[g] * C_DIM)[lane] = val;
            }
            uint2 u;
            u.x = packbf(val.x, val.y);
            u.y = packbf(val.z, val.w);
            *reinterpret_cast<uint2*>(g_xp_bf + (size_t)ipos * C_DIM + lane * 4) = u;
        }
    }
}

// ---------------------------------------------------------------------------
// qap: QKV -> attention -> proj fused, one block per partition, k=64 chunks.
// SMEM (words): qw 64x196 (12544) | xpw 64x68 (4352) | bW 2x4608 (9216,
//   stage0 aliased as VT during attention) | kfl 64.   Total 104.7 KB.
// ---------------------------------------------------------------------------
#define QW4 196
#define SAW 68
#define SBW64 36
#define BST64 (128 * SBW64)          // 4608 words per stage
#define QP_Q_OFF   0
#define QP_XP_OFF  (64 * QW4)
#define QP_B_OFF   (QP_XP_OFF + 64 * SAW)
#define QP_KFL_OFF (QP_B_OFF + 2 * BST64)
#define QP_SMEM_BYTES ((QP_KFL_OFF + 64) * 4)

__global__ void __launch_bounds__(256) qap_kernel(
    const __nv_bfloat16* __restrict__ Ab, const __nv_bfloat16* __restrict__ WqkvT,
    const float* __restrict__ qkvb,
    const __nv_bfloat16* __restrict__ WprojT, const float* __restrict__ projb,
    const float* __restrict__ g1, float* __restrict__ outv)
{
    extern __shared__ uint32_t smu[];
    uint32_t* qw  = smu + QP_Q_OFF;
    uint32_t* xpw = smu + QP_XP_OFF;
    uint32_t* bW  = smu + QP_B_OFF;
    int* kfl = (int*)(smu + QP_KFL_OFF);

    int m   = blockIdx.x;
    int tid = threadIdx.x;
    int lane = tid & 31;
    int wid  = tid >> 5;
    int g    = lane >> 2;
    int tg   = lane & 3;
    int wr2  = wid >> 2;     // 0..1
    int wc2  = wid & 3;      // 0..3
    size_t r0 = (size_t)m * 64;

    uint32_t xp_u = smem_u32(xpw);
    uint32_t b_u  = smem_u32(bW);

    if (tid < 64) kfl[tid] = g_mflag[r0 + tid];

    // xp panel: 64 rows x 256B = 1024 16B txns
#pragma unroll
    for (int t = 0; t < 4; t++) {
        int idx = tid + t * 256;
        int r = idx >> 4, cc = idx & 15;
        cp_async16(xp_u + (uint32_t)(r * (SAW * 4) + cc * 16),
                   Ab + (r0 + r) * C_DIM + cc * 8);
    }
    // k64 B loaders: 128 rows x 128B per chunk = 1024 16B txns (FIXED)
    auto loadQB = [&](int nc, int kc, int s) {
#pragma unroll
        for (int t = 0; t < 4; t++) {
            int idx = tid + t * 256;
            int r = idx >> 3, cc = idx & 7;
            cp_async16(b_u + (uint32_t)(s * (BST64 * 4) + r * (SBW64 * 4) + cc * 16),
                       WqkvT + (size_t)(nc * 128 + r) * C_DIM + kc * 64 + cc * 8);
        }
        asm volatile("cp.async.commit_group;" ::: "memory");
    };
    auto loadPB = [&](int kc, int s) {
#pragma unroll
        for (int t = 0; t < 4; t++) {
            int idx = tid + t * 256;
            int r = idx >> 3, cc = idx & 7;
            cp_async16(b_u + (uint32_t)(s * (BST64 * 4) + r * (SBW64 * 4) + cc * 16),
                       WprojT + (size_t)r * C_DIM + kc * 64 + cc * 8);
        }
        asm volatile("cp.async.commit_group;" ::: "memory");
    };

    loadQB(0, 0, 0);   // group includes xp panel txns

    // ---- Phase 1: QKV GEMM, 3 n-chunks, 2 k64-chunks each ----
#pragma unroll 1
    for (int nc = 0; nc < 3; nc++) {
        if (nc > 0) loadQB(nc, 0, 0);
        float pc[2][4][4];
#pragma unroll
        for (int i = 0; i < 2; i++)
#pragma unroll
            for (int j = 0; j < 4; j++)
#pragma unroll
                for (int q = 0; q < 4; q++) pc[i][j][q] = 0.0f;

#pragma unroll
        for (int kc = 0; kc < 2; kc++) {
            int s = kc;
            if (kc == 0) {
                loadQB(nc, 1, 1);
                asm volatile("cp.async.wait_group 1;" ::: "memory");
            } else {
                asm volatile("cp.async.wait_group 0;" ::: "memory");
            }
            __syncthreads();
            const uint32_t* Bp = bW + s * BST64;
#pragma unroll
            for (int kk = 0; kk < 4; kk++) {
                int kwA = kc * 32 + kk * 8 + tg;
                int kwB = kk * 8 + tg;
                uint32_t a[2][4], b[4][2];
#pragma unroll
                for (int i = 0; i < 2; i++) {
                    int row = wr2 * 32 + i * 16 + g;
                    a[i][0] = xpw[row * SAW + kwA];
                    a[i][1] = xpw[(row + 8) * SAW + kwA];
                    a[i][2] = xpw[row * SAW + kwA + 4];
                    a[i][3] = xpw[(row + 8) * SAW + kwA + 4];
                }
#pragma unroll
                for (int j = 0; j < 4; j++) {
                    int n = wc2 * 32 + j * 8 + g;
                    b[j][0] = Bp[n * SBW64 + kwB];
                    b[j][1] = Bp[n * SBW64 + kwB + 4];
                }
#pragma unroll
                for (int i = 0; i < 2; i++)
#pragma unroll
                    for (int j = 0; j < 4; j++)
                        mma_bf16(pc[i][j], a[i], b[j]);
            }
            __syncthreads();
        }
        // epilogue -> qw (bf16)
#pragma unroll
        for (int i = 0; i < 2; i++)
#pragma unroll
            for (int half = 0; half < 2; half++) {
                int row = wr2 * 32 + i * 16 + g + half * 8;
#pragma unroll
                for (int j = 0; j < 4; j++) {
                    int colg = nc * 128 + wc2 * 32 + j * 8 + tg * 2;
                    float v0 = pc[i][j][half * 2]     + __ldg(&qkvb[colg]);
                    float v1 = pc[i][j][half * 2 + 1] + __ldg(&qkvb[colg + 1]);
                    qw[row * QW4 + (colg >> 1)] = packbf(v0, v1);
                }
            }
    }
    __syncthreads();

    // prefetch proj B chunk 0 into stage 1 (stage 0 becomes VT)
    loadPB(0, 1);

    // ---- Phase 2: build VT[h][d][key] into bW stage 0 ----
    {
        const __nv_bfloat16* qb = reinterpret_cast<const __nv_bfloat16*>(qw);
        __nv_bfloat16* vtb = reinterpret_cast<__nv_bfloat16*>(bW);
        for (int i = tid; i < 8192; i += 256) {
            int key = i >> 7, d = i & 127;
            int h = d >> 5, dd = d & 31;
            vtb[h * 2304 + dd * 72 + key] = qb[key * 392 + h * 96 + 64 + dd];
        }
    }
    __syncthreads();

    // ---- Phase 3: attention (register-resident P) ----
    int h = wid >> 1;
    int rbase = (wid & 1) * 32;
    int qh = h * 48, kh = h * 48 + 16;
    const uint32_t* vth = bW + h * (32 * SBW64);
    const float scale = 0.17677669529663687f;

    {
        float c[2][8][4];
#pragma unroll
        for (int i = 0; i < 2; i++)
#pragma unroll
            for (int j = 0; j < 8; j++)
#pragma unroll
                for (int q = 0; q < 4; q++) c[i][j][q] = 0.0f;

#pragma unroll
        for (int kq = 0; kq < 2; kq++) {
            uint32_t a[2][4], b[8][2];
#pragma unroll
            for (int i = 0; i < 2; i++) {
                int row = rbase + i * 16 + g;
                a[i][0] = qw[row * QW4 + qh + kq * 8 + tg];
                a[i][1] = qw[(row + 8) * QW4 + qh + kq * 8 + tg];
                a[i][2] = qw[row * QW4 + qh + kq * 8 + tg + 4];
                a[i][3] = qw[(row + 8) * QW4 + qh + kq * 8 + tg + 4];
            }
#pragma unroll
            for (int j = 0; j < 8; j++) {
                int n = j * 8 + g;
                b[j][0] = qw[n * QW4 + kh + kq * 8 + tg];
                b[j][1] = qw[n * QW4 + kh + kq * 8 + tg + 4];
            }
#pragma unroll
            for (int i = 0; i < 2; i++)
#pragma unroll
                for (int j = 0; j < 8; j++)
                    mma_bf16(c[i][j], a[i], b[j]);
        }

        unsigned mask = 0;
#pragma unroll
        for (int j = 0; j < 8; j++)
#pragma unroll
            for (int q = 0; q < 2; q++)
                if (kfl[j * 8 + 2 * tg + q] == 2) mask |= 1u << (j * 2 + q);

#pragma unroll
        for (int i = 0; i < 2; i++)
#pragma unroll
            for (int sel = 0; sel < 2; sel++) {
                float mx = -1e30f;
#pragma unroll
                for (int j = 0; j < 8; j++)
#pragma unroll
                    for (int q = 0; q < 2; q++) {
                        float v = c[i][j][sel * 2 + q] * scale;
                        if (mask & (1u << (j * 2 + q))) v = -10000.0f;
                        c[i][j][sel * 2 + q] = v;
                        mx = fmaxf(mx, v);
                    }
                mx = fmaxf(mx, __shfl_xor_sync(0xffffffffu, mx, 1));
                mx = fmaxf(mx, __shfl_xor_sync(0xffffffffu, mx, 2));
                float s = 0.0f;
#pragma unroll
                for (int j = 0; j < 8; j++)
#pragma unroll
                    for (int q = 0; q < 2; q++) {
                        float e = __expf(c[i][j][sel * 2 + q] - mx);
                        c[i][j][sel * 2 + q] = e;
                        s += e;
                    }
                s += __shfl_xor_sync(0xffffffffu, s, 1);
                s += __shfl_xor_sync(0xffffffffu, s, 2);
                float rinv = 1.0f / s;
#pragma unroll
                for (int j = 0; j < 8; j++)
#pragma unroll
                    for (int q = 0; q < 2; q++)
                        c[i][j][sel * 2 + q] *= rinv;
            }

        float o[2][4][4];
#pragma unroll
        for (int i = 0; i < 2; i++)
#pragma unroll
            for (int j = 0; j < 4; j++)
#pragma unroll
                for (int q = 0; q < 4; q++) o[i][j][q] = 0.0f;

#pragma unroll
        for (int kp = 0; kp < 4; kp++) {
            uint32_t b[4][2];
#pragma unroll
            for (int j = 0; j < 4; j++) {
                int n = j * 8 + g;
                b[j][0] = vth[n * SBW64 + kp * 8 + tg];
                b[j][1] = vth[n * SBW64 + kp * 8 + tg + 4];
            }
#pragma unroll
            for (int i = 0; i < 2; i++) {
                uint32_t a[4];
                a[0] = packbf(c[i][2 * kp][0],     c[i][2 * kp][1]);
                a[1] = packbf(c[i][2 * kp][2],     c[i][2 * kp][3]);
                a[2] = packbf(c[i][2 * kp + 1][0], c[i][2 * kp + 1][1]);
                a[3] = packbf(c[i][2 * kp + 1][2], c[i][2 * kp + 1][3]);
#pragma unroll
                for (int j = 0; j < 4; j++)
                    mma_bf16(o[i][j], a, b[j]);
            }
        }

        // O into xpw (xp panel dead after QKV)
#pragma unroll
        for (int i = 0; i < 2; i++)
#pragma unroll
            for (int j = 0; j < 4; j++) {
                int row = rbase + i * 16 + g;
                int wrd = h * 16 + j * 4 + tg;
                xpw[row * SAW + wrd]       = packbf(o[i][j][0], o[i][j][1]);
                xpw[(row + 8) * SAW + wrd] = packbf(o[i][j][2], o[i][j][3]);
            }
    }
    __syncthreads();     // VT dead beyond this point

    // ---- Phase 4: proj GEMM (64x128, 2 k64-chunks) + scatter ----
    {
        float pc[2][4][4];
#pragma unroll
        for (int i = 0; i < 2; i++)
#pragma unroll
            for (int j = 0; j < 4; j++)
#pragma unroll
                for (int q = 0; q < 4; q++) pc[i][j][q] = 0.0f;

#pragma unroll
        for (int kc = 0; kc < 2; kc++) {
            int s = kc ^ 1;    // kc0 from stage1 (prefetched), kc1 from stage0
            if (kc == 0) {
                loadPB(1, 0);
                asm volatile("cp.async.wait_group 1;" ::: "memory");
            } else {
                asm volatile("cp.async.wait_group 0;" ::: "memory");
            }
            __syncthreads();
            const uint32_t* Bp = bW + s * BST64;
#pragma unroll
            for (int kk = 0; kk < 4; kk++) {
                int kwA = kc * 32 + kk * 8 + tg;
                int kwB = kk * 8 + tg;
                uint32_t a[2][4], b[4][2];
#pragma unroll
                for (int i = 0; i < 2; i++) {
                    int row = wr2 * 32 + i * 16 + g;
                    a[i][0] = xpw[row * SAW + kwA];
                    a[i][1] = xpw[(row + 8) * SAW + kwA];
                    a[i][2] = xpw[row * SAW + kwA + 4];
                    a[i][3] = xpw[(row + 8) * SAW + kwA + 4];
                }
#pragma unroll
                for (int j = 0; j < 4; j++) {
                    int n = wc2 * 32 + j * 8 + g;
                    b[j][0] = Bp[n * SBW64 + kwB];
                    b[j][1] = Bp[n * SBW64 + kwB + 4];
                }
#pragma unroll
                for (int i = 0; i < 2; i++)
#pragma unroll
                    for (int j = 0; j < 4; j++)
                        mma_bf16(pc[i][j], a[i], b[j]);
            }
            if (kc == 0) __syncthreads();
        }

#pragma unroll
        for (int i = 0; i < 2; i++)
#pragma unroll
            for (int half = 0; half < 2; half++) {
                int lrow = wr2 * 32 + i * 16 + g + half * 8;
                size_t grow = r0 + lrow;
                int f = kfl[lrow];
                if (f == 2) continue;
                if (f == 1) {
                    size_t rank = (size_t)g_mrank[grow];
#pragma unroll
                    for (int j = 0; j < 4; j++) {
                        int colg = wc2 * 32 + j * 8 + tg * 2;
                        float v0 = pc[i][j][half * 2]     + __ldg(&projb[colg]);
                        float v1 = pc[i][j][half * 2 + 1] + __ldg(&projb[colg + 1]);
                        v0 = g_xa[rank * C_DIM + colg]     + __ldg(&g1[colg]) * v0;
                        v1 = g_xa[rank * C_DIM + colg + 1] + __ldg(&g1[colg + 1]) * v1;
                        *reinterpret_cast<float2*>(g_y + rank * C_DIM + colg) =
                            make_float2(v0, v1);
                    }
                } else {
                    float* dstf = outv + (size_t)g_mrow[grow] * C_DIM;
#pragma unroll
                    for (int j = 0; j < 4; j++) {
                        int colg = wc2 * 32 + j * 8 + tg * 2;
                        float v0 = pc[i][j][half * 2]     + __ldg(&projb[colg]);
                        float v1 = pc[i][j][half * 2 + 1] + __ldg(&projb[colg + 1]);
                        *reinterpret_cast<float2*>(dstf + colg) = make_float2(v0, v1);
                    }
                }
            }
    }
}

// ---------------------------------------------------------------------------
// mlpf: LN2 -> MLP1(gelu) -> MLP2 + residual scatter, block = 64 asy rows.
// SMEM (words): awB region 4608 (aw uses 64x68=4352; MLP2 B stage 1) |
//   hw 64x260 (16640) | bW 5120 (MLP1: 2x k32 stages; MLP2: stage 0 k64)
// Total 26368 words = 105.5 KB.
// ---------------------------------------------------------------------------
#define SHW 260
#define SBW 20
#define BSTG (128 * SBW)            // 2560-word k32 stage (MLP1)
#define MF_A_OFF 0
#define MF_H_OFF 4608
#define MF_B_OFF (MF_H_OFF + 64 * SHW)
#define MF_SMEM_BYTES ((MF_B_OFF + 2 * BSTG) * 4)

__global__ void __launch_bounds__(256) mlpf_kernel(
    const __nv_bfloat16* __restrict__ W1T, const float* __restrict__ b1,
    const __nv_bfloat16* __restrict__ W2T, const float* __restrict__ b2,
    const float* __restrict__ ln2w, const float* __restrict__ ln2b,
    const float* __restrict__ g2, float* __restrict__ outv)
{
    extern __shared__ uint32_t smu[];
    uint32_t* aw = smu + MF_A_OFF;
    uint32_t* hw = smu + MF_H_OFF;
    uint32_t* bW = smu + MF_B_OFF;

    int tid  = threadIdx.x;
    int lane = tid & 31;
    int wid  = tid >> 5;
    int g    = lane >> 2;
    int tg   = lane & 3;
    int wr2  = wid >> 2;
    int wc2  = wid & 3;
    size_t m0 = (size_t)blockIdx.x * 64;

    uint32_t smu_u = smem_u32(smu);
    uint32_t b_u = smu_u + MF_B_OFF * 4;

    auto loadB1 = [&](int nc, int kc, int s) {
#pragma unroll
        for (int t = 0; t < 2; t++) {
            int idx = tid + t * 256;
            int r = idx >> 2, cc = idx & 3;
            cp_async16(b_u + (uint32_t)(s * (BSTG * 4) + r * (SBW * 4) + cc * 16),
                       W1T + (size_t)(nc * 128 + r) * C_DIM + kc * 32 + cc * 8);
        }
        asm volatile("cp.async.commit_group;" ::: "memory");
    };
    // MLP2 k64 loader (1024 txns, FIXED): s==0 -> bW region, s==1 -> aw region
    auto loadB2 = [&](int kc, int s) {
        uint32_t base = s ? smu_u : b_u;
#pragma unroll
        for (int t = 0; t < 4; t++) {
            int idx = tid + t * 256;
            int r = idx >> 3, cc = idx & 7;
            cp_async16(base + (uint32_t)(r * (SBW64 * 4) + cc * 16),
                       W2T + (size_t)r * 512 + kc * 64 + cc * 8);
        }
        asm volatile("cp.async.commit_group;" ::: "memory");
    };

    loadB1(0, 0, 0);

    // LN2 over g_y -> bf16 A panel (warp per 8 rows)
    {
        float4 wv = reinterpret_cast<const float4*>(ln2w)[lane];
        float4 bv = reinterpret_cast<const float4*>(ln2b)[lane];
        for (int it = 0; it < 8; it++) {
            int r = wid * 8 + it;
            float4 v = reinterpret_cast<const float4*>(g_y + (m0 + r) * C_DIM)[lane];
            float s1 = v.x + v.y + v.z + v.w;
            float s2 = v.x*v.x + v.y*v.y + v.z*v.z + v.w*v.w;
            warp_sum2(s1, s2);
            float m = s1 * (1.0f / C_DIM);
            float var = s2 * (1.0f / C_DIM) - m * m;
            float inv = rsqrtf(var + EPS_LN);
            aw[r * SAW + lane * 2] = packbf(
                (v.x - m) * inv * wv.x + bv.x, (v.y - m) * inv * wv.y + bv.y);
            aw[r * SAW + lane * 2 + 1] = packbf(
                (v.z - m) * inv * wv.z + bv.z, (v.w - m) * inv * wv.w + bv.w);
        }
    }

    // ---- MLP1: 4 n-chunks of 128, k32 double-buffered, gelu -> hw ----
#pragma unroll 1
    for (int nc = 0; nc < 4; nc++) {
        if (nc > 0) loadB1(nc, 0, 0);
        float pc[2][4][4];
#pragma unroll
        for (int i = 0; i < 2; i++)
#pragma unroll
            for (int j = 0; j < 4; j++)
#pragma unroll
                for (int q = 0; q < 4; q++) pc[i][j][q] = 0.0f;

#pragma unroll
        for (int kc = 0; kc < 4; kc++) {
            int s = kc & 1;
            if (kc < 3) {
                loadB1(nc, kc + 1, s ^ 1);
                asm volatile("cp.async.wait_group 1;" ::: "memory");
            } else {
                asm volatile("cp.async.wait_group 0;" ::: "memory");
            }
            __syncthreads();
            const uint32_t* Bp = bW + s * BSTG;
#pragma unroll
            for (int kk = 0; kk < 2; kk++) {
                int kw = kc * 16 + kk * 8 + tg;
                uint32_t a[2][4], b[4][2];
#pragma unroll
                for (int i = 0; i < 2; i++) {
                    int row = wr2 * 32 + i * 16 + g;
                    a[i][0] = aw[row * SAW + kw];
                    a[i][1] = aw[(row + 8) * SAW + kw];
                    a[i][2] = aw[row * SAW + kw + 4];
                    a[i][3] = aw[(row + 8) * SAW + kw + 4];
                }
#pragma unroll
                for (int j = 0; j < 4; j++) {
                    int n = wc2 * 32 + j * 8 + g;
                    b[j][0] = Bp[n * SBW + kk * 8 + tg];
                    b[j][1] = Bp[n * SBW + kk * 8 + tg + 4];
                }
#pragma unroll
                for (int i = 0; i < 2; i++)
#pragma unroll
                    for (int j = 0; j < 4; j++)
                        mma_bf16(pc[i][j], a[i], b[j]);
            }
            __syncthreads();
        }
#pragma unroll
        for (int i = 0; i < 2; i++)
#pragma unroll
            for (int half = 0; half < 2; half++) {
                int row = wr2 * 32 + i * 16 + g + half * 8;
#pragma unroll
                for (int j = 0; j < 4; j++) {
                    int colg = nc * 128 + wc2 * 32 + j * 8 + tg * 2;
                    float v0 = pc[i][j][half * 2]     + __ldg(&b1[colg]);
                    float v1 = pc[i][j][half * 2 + 1] + __ldg(&b1[colg + 1]);
                    v0 = 0.5f * v0 * (1.0f + erff(v0 * 0.7071067811865476f));
                    v1 = 0.5f * v1 * (1.0f + erff(v1 * 0.7071067811865476f));
                    hw[row * SHW + (colg >> 1)] = packbf(v0, v1);
                }
            }
    }
    __syncthreads();

    loadB2(0, 0);

    // ---- MLP2: 64x128, K=512 as 8 k64-chunks, stage1 aliased into aw ----
    {
        float pc[2][4][4];
#pragma unroll
        for (int i = 0; i < 2; i++)
#pragma unroll
            for (int j = 0; j < 4; j++)
#pragma unroll
                for (int q = 0; q < 4; q++) pc[i][j][q] = 0.0f;

#pragma unroll 1
        for (int kc = 0; kc < 8; kc++) {
            int s = kc & 1;
            if (kc + 1 < 8) {
                loadB2(kc + 1, s ^ 1);
                asm volatile("cp.async.wait_group 1;" ::: "memory");
            } else {
                asm volatile("cp.async.wait_group 0;" ::: "memory");
            }
            __syncthreads();
            const uint32_t* Bp = s ? smu : bW;
#pragma unroll
            for (int kk = 0; kk < 4; kk++) {
                int kwA = kc * 32 + kk * 8 + tg;
                int kwB = kk * 8 + tg;
                uint32_t a[2][4], b[4][2];
#pragma unroll
                for (int i = 0; i < 2; i++) {
                    int row = wr2 * 32 + i * 16 + g;
                    a[i][0] = hw[row * SHW + kwA];
                    a[i][1] = hw[(row + 8) * SHW + kwA];
                    a[i][2] = hw[row * SHW + kwA + 4];
                    a[i][3] = hw[(row + 8) * SHW + kwA + 4];
                }
#pragma unroll
                for (int j = 0; j < 4; j++) {
                    int n = wc2 * 32 + j * 8 + g;
                    b[j][0] = Bp[n * SBW64 + kwB];
                    b[j][1] = Bp[n * SBW64 + kwB + 4];
                }
#pragma unroll
                for (int i = 0; i < 2; i++)
#pragma unroll
                    for (int j = 0; j < 4; j++)
                        mma_bf16(pc[i][j], a[i], b[j]);
            }
            if (kc + 1 < 8) __syncthreads();
        }

#pragma unroll
        for (int i = 0; i < 2; i++)
#pragma unroll
            for (int half = 0; half < 2; half++) {
                size_t grow = m0 + wr2 * 32 + i * 16 + g + half * 8;
                float* dstf = outv + (size_t)g_asyrow[grow] * C_DIM;
#pragma unroll
                for (int j = 0; j < 4; j++) {
                    int colg = wc2 * 32 + j * 8 + tg * 2;
                    float v0 = pc[i][j][half * 2]     + __ldg(&b2[colg]);
                    float v1 = pc[i][j][half * 2 + 1] + __ldg(&b2[colg + 1]);
                    v0 = g_y[grow * C_DIM + colg]     + __ldg(&g2[colg]) * v0;
                    v1 = g_y[grow * C_DIM + colg + 1] + __ldg(&g2[colg + 1]) * v1;
                    *reinterpret_cast<float2*>(dstf + colg) = make_float2(v0, v1);
                }
            }
    }
}

// ---------------------------------------------------------------------------
extern "C" void kernel_launch(void* const* d_in, const int* in_sizes, int n_in,
                              void* d_out, int out_size)
{
    int base = 7;
    if (n_in == 19) base = 5;

    const float* x      = (const float*)d_in[0];
    const int*   iw     = (const int*)d_in[1];
    const int*   ipart  = (const int*)d_in[2];
    const int*   asy    = (const int*)d_in[3];
    const int*   blk    = (const int*)d_in[4];
    const float* ln1w   = (const float*)d_in[base + 0];
    const float* ln1b   = (const float*)d_in[base + 1];
    const float* qkvw   = (const float*)d_in[base + 2];
    const float* qkvb   = (const float*)d_in[base + 3];
    const float* projw  = (const float*)d_in[base + 4];
    const float* projb  = (const float*)d_in[base + 5];
    const float* g1     = (const float*)d_in[base + 6];
    const float* ln2w   = (const float*)d_in[base + 7];
    const float* ln2b   = (const float*)d_in[base + 8];
    const float* w1     = (const float*)d_in[base + 9];
    const float* b1     = (const float*)d_in[base + 10];
    const float* w2     = (const float*)d_in[base + 11];
    const float* b2     = (const float*)d_in[base + 12];
    const float* g2     = (const float*)d_in[base + 13];
    float* out = (float*)d_out;

    __nv_bfloat16 *p_xp, *p_wqkvT, *p_wprojT, *p_w1T, *p_w2T;
    cudaGetSymbolAddress((void**)&p_xp, g_xp_bf);
    cudaGetSymbolAddress((void**)&p_wqkvT, g_wqkvT);
    cudaGetSymbolAddress((void**)&p_wprojT, g_wprojT);
    cudaGetSymbolAddress((void**)&p_w1T, g_w1T);
    cudaGetSymbolAddress((void**)&p_w2T, g_w2T);

    cudaFuncSetAttribute(qap_kernel,
                         cudaFuncAttributeMaxDynamicSharedMemorySize, QP_SMEM_BYTES);
    cudaFuncSetAttribute(mlpf_kernel,
                         cudaFuncAttributeMaxDynamicSharedMemorySize, MF_SMEM_BYTES);

    // 0-2. init + maps + meta + merged weight transpose
    zero_misc_kernel<<<(MW_CNT / 16 + N_WIN / 4 + 255) / 256, 256>>>();
    set_maps_kernel<<<MW_CNT / 256, 256>>>(asy, blk, iw, ipart);
    meta_kernel<<<MW_CNT / 256, 256>>>(ipart, iw);
    wtrans_all_kernel<<<768, 256>>>(qkvw, projw, w1, w2,
                                    p_wqkvT, p_wprojT, p_w1T, p_w2T);
    // 3. fused LN + double-LN + scatter
    ln_kernel<<<N_TOK / 16, 256>>>(x, ln1w, ln1b, out);
    // 4. QKV -> attention -> proj fused (per partition)
    qap_kernel<<<M_PART, 256, QP_SMEM_BYTES>>>(
        p_xp, p_wqkvT, qkvb, p_wprojT, projb, g1, out);
    // 5. LN2 -> MLP1 -> MLP2 fused (per 64 asy rows)
    mlpf_kernel<<<A_CNT / 64, 256, MF_SMEM_BYTES>>>(
        p_w1T, b1, p_w2T, b2, ln2w, ln2b, g2, out);
}

// round 16
// speedup vs baseline: 1.3206x; 1.0130x over previous
#include <cuda_runtime.h>
#include <cuda_bf16.h>
#include <math.h>
#include <stdint.h>

// Problem constants
#define N_TOK   524288
#define N_WIN   8192
#define P_TOK   64
#define C_DIM   128
#define M_PART  4096
#define MW_CNT  262144
#define A_CNT   131072
#define BL_CNT  65536
#define EPS_LN  1e-6f

// ---------------------------------------------------------------------------
// Scratch (device globals — allocation-free rule)
// ---------------------------------------------------------------------------
__device__ float g_xa[(size_t)A_CNT * C_DIM];
__device__ float g_y[(size_t)A_CNT * C_DIM];
__device__ __nv_bfloat16 g_xp_bf[(size_t)MW_CNT * C_DIM];
__device__ __nv_bfloat16 g_wqkvT[384 * 128];
__device__ __nv_bfloat16 g_wprojT[128 * 128];
__device__ __nv_bfloat16 g_w1T[512 * 128];
__device__ __nv_bfloat16 g_w2T[128 * 512];
__device__ unsigned char g_flag[MW_CNT];
__device__ int g_rank[MW_CNT];
__device__ int g_ipos[MW_CNT];
__device__ int g_winv[N_WIN];
__device__ int g_asyrow[A_CNT];
__device__ unsigned char g_mflag[MW_CNT];
__device__ int g_mrow[MW_CNT];
__device__ int g_mrank[MW_CNT];

// ---------------------------------------------------------------------------
// helpers
// ---------------------------------------------------------------------------
__device__ __forceinline__ void mma_bf16(float c[4], const uint32_t a[4], const uint32_t b[2]) {
    asm volatile(
        "mma.sync.aligned.m16n8k16.row.col.f32.bf16.bf16.f32 "
        "{%0,%1,%2,%3}, {%4,%5,%6,%7}, {%8,%9}, {%0,%1,%2,%3};"
        : "+f"(c[0]), "+f"(c[1]), "+f"(c[2]), "+f"(c[3])
        : "r"(a[0]), "r"(a[1]), "r"(a[2]), "r"(a[3]), "r"(b[0]), "r"(b[1]));
}
__device__ __forceinline__ uint32_t smem_u32(const void* p) {
    uint32_t a;
    asm("{ .reg .u64 t; cvta.to.shared.u64 t, %1; cvt.u32.u64 %0, t; }" : "=r"(a) : "l"(p));
    return a;
}
__device__ __forceinline__ void cp_async16(uint32_t dst, const void* src) {
    asm volatile("cp.async.cg.shared.global [%0], [%1], 16;" :: "r"(dst), "l"(src) : "memory");
}
__device__ __forceinline__ uint32_t packbf(float a, float b) {
    __nv_bfloat162 p = __floats2bfloat162_rn(a, b);
    return *reinterpret_cast<uint32_t*>(&p);
}
__device__ __forceinline__ void warp_sum2(float& s1, float& s2) {
#pragma unroll
    for (int o = 16; o; o >>= 1) {
        s1 += __shfl_xor_sync(0xffffffffu, s1, o);
        s2 += __shfl_xor_sync(0xffffffffu, s2, o);
    }
}
__device__ __forceinline__ void warp_sum4(float& a1, float& a2, float& b1, float& b2) {
#pragma unroll
    for (int o = 16; o; o >>= 1) {
        a1 += __shfl_xor_sync(0xffffffffu, a1, o);
        a2 += __shfl_xor_sync(0xffffffffu, a2, o);
        b1 += __shfl_xor_sync(0xffffffffu, b1, o);
        b2 += __shfl_xor_sync(0xffffffffu, b2, o);
    }
}

// ---------------------------------------------------------------------------
// K0/K1/K2: init, maps, meta
// ---------------------------------------------------------------------------
__global__ void __launch_bounds__(256) zero_misc_kernel()
{
    int t = blockIdx.x * 256 + threadIdx.x;
    if (t < MW_CNT / 16)
        reinterpret_cast<uint4*>(g_flag)[t] = make_uint4(0u, 0u, 0u, 0u);
    int u = t - MW_CNT / 16;
    if (u >= 0 && u < N_WIN / 4)
        reinterpret_cast<int4*>(g_winv)[u] = make_int4(-1, -1, -1, -1);
}
__global__ void __launch_bounds__(256) set_maps_kernel(
    const int* __restrict__ asy, const int* __restrict__ blk,
    const int* __restrict__ iw, const int* __restrict__ ipart)
{
    int t = blockIdx.x * 256 + threadIdx.x;
    if (t < MW_CNT) g_ipos[ipart[t]] = t;
    if (t < A_CNT) {
        int g = asy[t];
        g_flag[g] = 1;
        g_rank[g] = t;
        g_asyrow[t] = iw[g >> 6] * 64 + (g & 63);
    } else if (t < A_CNT + BL_CNT) {
        g_flag[blk[t - A_CNT]] = 2;
    }
    if (t < M_PART) g_winv[iw[t]] = t;
}
__global__ void __launch_bounds__(256) meta_kernel(
    const int* __restrict__ ipart, const int* __restrict__ iw)
{
    int i = blockIdx.x * 256 + threadIdx.x;
    if (i >= MW_CNT) return;
    int g = ipart[i];
    int f = g_flag[g];
    g_mflag[i] = (unsigned char)f;
    g_mrow[i]  = iw[g >> 6] * 64 + (g & 63);
    g_mrank[i] = (f == 1) ? g_rank[g] : 0;
}

// ---------------------------------------------------------------------------
// K2b: ALL weight transposes in one launch
// ---------------------------------------------------------------------------
__global__ void __launch_bounds__(256) wtrans_all_kernel(
    const float* __restrict__ qkvw, const float* __restrict__ projw,
    const float* __restrict__ w1, const float* __restrict__ w2,
    __nv_bfloat16* __restrict__ oq, __nv_bfloat16* __restrict__ op,
    __nv_bfloat16* __restrict__ o1, __nv_bfloat16* __restrict__ o2)
{
    int idx = blockIdx.x * 256 + threadIdx.x;
    const float* W; __nv_bfloat16* WT; int K, N, local;
    if (idx < 49152)       { W = qkvw;  WT = oq; K = 128; N = 384; local = idx; }
    else if (idx < 65536)  { W = projw; WT = op; K = 128; N = 128; local = idx - 49152; }
    else if (idx < 131072) { W = w1;    WT = o1; K = 128; N = 512; local = idx - 65536; }
    else                   { W = w2;    WT = o2; K = 512; N = 128; local = idx - 131072; }
    int k = local / N, n = local - k * N;
    WT[n * K + k] = __float2bfloat16(W[(size_t)k * N + n]);
}

// ---------------------------------------------------------------------------
// K3: fused LN + scatter (unchanged)
// ---------------------------------------------------------------------------
__global__ void __launch_bounds__(256) ln_kernel(
    const float* __restrict__ x, const float* __restrict__ w,
    const float* __restrict__ b, float* __restrict__ out)
{
    int wglob = blockIdx.x * 8 + (threadIdx.x >> 5);
    int lane  = threadIdx.x & 31;
    int r0 = wglob * 2;
    int r1 = r0 + 1;

    float4 v0 = reinterpret_cast<const float4*>(x + (size_t)r0 * C_DIM)[lane];
    float4 v1 = reinterpret_cast<const float4*>(x + (size_t)r1 * C_DIM)[lane];
    float4 wv = reinterpret_cast<const float4*>(w)[lane];
    float4 bv = reinterpret_cast<const float4*>(b)[lane];

    float a1 = v0.x + v0.y + v0.z + v0.w;
    float a2 = v0.x*v0.x + v0.y*v0.y + v0.z*v0.z + v0.w*v0.w;
    float c1 = v1.x + v1.y + v1.z + v1.w;
    float c2 = v1.x*v1.x + v1.y*v1.y + v1.z*v1.z + v1.w*v1.w;
    warp_sum4(a1, a2, c1, c2);

#pragma unroll
    for (int rr = 0; rr < 2; rr++) {
        int row = rr ? r1 : r0;
        float4 v = rr ? v1 : v0;
        float s1 = rr ? c1 : a1;
        float s2 = rr ? c2 : a2;
        float m = s1 * (1.0f / C_DIM);
        float var = s2 * (1.0f / C_DIM) - m * m;
        float inv = rsqrtf(var + EPS_LN);
        float4 r;
        r.x = (v.x - m) * inv * wv.x + bv.x; r.y = (v.y - m) * inv * wv.y + bv.y;
        r.z = (v.z - m) * inv * wv.z + bv.z; r.w = (v.w - m) * inv * wv.w + bv.w;

        int n = row >> 6, p = row & 63;
        int widx = g_winv[n];
        if (widx < 0) {
            reinterpret_cast<float4*>(out + (size_t)row * C_DIM)[lane] = r;
        } else {
            int g = widx * 64 + p;
            int f = g_flag[g];
            int ipos = g_ipos[g];
            float4 val = r;
            if (f == 2) {
                reinterpret_cast<float4*>(out + (size_t)row * C_DIM)[lane] = r;
            } else if (f == 1) {
                float t1 = r.x + r.y + r.z + r.w;
                float t2 = r.x*r.x + r.y*r.y + r.z*r.z + r.w*r.w;
                warp_sum2(t1, t2);
                float m2 = t1 * (1.0f / C_DIM);
                float var2 = t2 * (1.0f / C_DIM) - m2 * m2;
                float inv2 = rsqrtf(var2 + EPS_LN);
                val.x = (r.x - m2) * inv2 * wv.x + bv.x;
                val.y = (r.y - m2) * inv2 * wv.y + bv.y;
                val.z = (r.z - m2) * inv2 * wv.z + bv.z;
                val.w = (r.w - m2) * inv2 * wv.w + bv.w;
                reinterpret_cast<float4*>(g_xa + (size_t)g_rank[g] * C_DIM)[lane] = val;
            }
            uint2 u;
            u.x = packbf(val.x, val.y);
            u.y = packbf(val.z, val.w);
            *reinterpret_cast<uint2*>(g_xp_bf + (size_t)ipos * C_DIM + lane * 4) = u;
        }
    }
}

// ---------------------------------------------------------------------------
// qap: QKV -> attention -> proj fused, one block per partition, k=64 chunks,
// cross-n-chunk B prefetch. SMEM unchanged from R15 (104.7 KB).
// ---------------------------------------------------------------------------
#define QW4 196
#define SAW 68
#define SBW64 36
#define BST64 (128 * SBW64)          // 4608 words per stage
#define QP_Q_OFF   0
#define QP_XP_OFF  (64 * QW4)
#define QP_B_OFF   (QP_XP_OFF + 64 * SAW)
#define QP_KFL_OFF (QP_B_OFF + 2 * BST64)
#define QP_SMEM_BYTES ((QP_KFL_OFF + 64) * 4)

__global__ void __launch_bounds__(256) qap_kernel(
    const __nv_bfloat16* __restrict__ Ab, const __nv_bfloat16* __restrict__ WqkvT,
    const float* __restrict__ qkvb,
    const __nv_bfloat16* __restrict__ WprojT, const float* __restrict__ projb,
    const float* __restrict__ g1, float* __restrict__ outv)
{
    extern __shared__ uint32_t smu[];
    uint32_t* qw  = smu + QP_Q_OFF;
    uint32_t* xpw = smu + QP_XP_OFF;
    uint32_t* bW  = smu + QP_B_OFF;
    int* kfl = (int*)(smu + QP_KFL_OFF);

    int m   = blockIdx.x;
    int tid = threadIdx.x;
    int lane = tid & 31;
    int wid  = tid >> 5;
    int g    = lane >> 2;
    int tg   = lane & 3;
    int wr2  = wid >> 2;     // 0..1
    int wc2  = wid & 3;      // 0..3
    size_t r0 = (size_t)m * 64;

    uint32_t xp_u = smem_u32(xpw);
    uint32_t b_u  = smem_u32(bW);

    if (tid < 64) kfl[tid] = g_mflag[r0 + tid];

    // xp panel: 64 rows x 256B = 1024 16B txns
#pragma unroll
    for (int t = 0; t < 4; t++) {
        int idx = tid + t * 256;
        int r = idx >> 4, cc = idx & 15;
        cp_async16(xp_u + (uint32_t)(r * (SAW * 4) + cc * 16),
                   Ab + (r0 + r) * C_DIM + cc * 8);
    }
    // k64 B loaders: 128 rows x 128B per chunk = 1024 16B txns
    auto loadQB = [&](int nc, int kc, int s) {
#pragma unroll
        for (int t = 0; t < 4; t++) {
            int idx = tid + t * 256;
            int r = idx >> 3, cc = idx & 7;
            cp_async16(b_u + (uint32_t)(s * (BST64 * 4) + r * (SBW64 * 4) + cc * 16),
                       WqkvT + (size_t)(nc * 128 + r) * C_DIM + kc * 64 + cc * 8);
        }
        asm volatile("cp.async.commit_group;" ::: "memory");
    };
    auto loadPB = [&](int kc, int s) {
#pragma unroll
        for (int t = 0; t < 4; t++) {
            int idx = tid + t * 256;
            int r = idx >> 3, cc = idx & 7;
            cp_async16(b_u + (uint32_t)(s * (BST64 * 4) + r * (SBW64 * 4) + cc * 16),
                       WprojT + (size_t)r * C_DIM + kc * 64 + cc * 8);
        }
        asm volatile("cp.async.commit_group;" ::: "memory");
    };

    loadQB(0, 0, 0);   // group includes xp panel txns

    // ---- Phase 1: QKV GEMM, 3 n-chunks, 2 k64-chunks, cross-nc prefetch ----
#pragma unroll 1
    for (int nc = 0; nc < 3; nc++) {
        float pc[2][4][4];
#pragma unroll
        for (int i = 0; i < 2; i++)
#pragma unroll
            for (int j = 0; j < 4; j++)
#pragma unroll
                for (int q = 0; q < 4; q++) pc[i][j][q] = 0.0f;

#pragma unroll
        for (int kc = 0; kc < 2; kc++) {
            if (kc == 0) {
                loadQB(nc, 1, 1);
                asm volatile("cp.async.wait_group 1;" ::: "memory");
            } else if (nc < 2) {
                loadQB(nc + 1, 0, 0);   // prefetch next n-chunk's k0
                asm volatile("cp.async.wait_group 1;" ::: "memory");
            } else {
                asm volatile("cp.async.wait_group 0;" ::: "memory");
            }
            __syncthreads();
            const uint32_t* Bp = bW + kc * BST64;
#pragma unroll
            for (int kk = 0; kk < 4; kk++) {
                int kwA = kc * 32 + kk * 8 + tg;
                int kwB = kk * 8 + tg;
                uint32_t a[2][4], b[4][2];
#pragma unroll
                for (int i = 0; i < 2; i++) {
                    int row = wr2 * 32 + i * 16 + g;
                    a[i][0] = xpw[row * SAW + kwA];
                    a[i][1] = xpw[(row + 8) * SAW + kwA];
                    a[i][2] = xpw[row * SAW + kwA + 4];
                    a[i][3] = xpw[(row + 8) * SAW + kwA + 4];
                }
#pragma unroll
                for (int j = 0; j < 4; j++) {
                    int n = wc2 * 32 + j * 8 + g;
                    b[j][0] = Bp[n * SBW64 + kwB];
                    b[j][1] = Bp[n * SBW64 + kwB + 4];
                }
#pragma unroll
                for (int i = 0; i < 2; i++)
#pragma unroll
                    for (int j = 0; j < 4; j++)
                        mma_bf16(pc[i][j], a[i], b[j]);
            }
            __syncthreads();
        }
        // epilogue -> qw (bf16)
#pragma unroll
        for (int i = 0; i < 2; i++)
#pragma unroll
            for (int half = 0; half < 2; half++) {
                int row = wr2 * 32 + i * 16 + g + half * 8;
#pragma unroll
                for (int j = 0; j < 4; j++) {
                    int colg = nc * 128 + wc2 * 32 + j * 8 + tg * 2;
                    float v0 = pc[i][j][half * 2]     + __ldg(&qkvb[colg]);
                    float v1 = pc[i][j][half * 2 + 1] + __ldg(&qkvb[colg + 1]);
                    qw[row * QW4 + (colg >> 1)] = packbf(v0, v1);
                }
            }
    }
    __syncthreads();

    // prefetch proj B chunk 0 into stage 1 (stage 0 becomes VT)
    loadPB(0, 1);

    // ---- Phase 2: build VT[h][d][key] into bW stage 0 (word-packed) ----
    {
        const __nv_bfloat16* qb = reinterpret_cast<const __nv_bfloat16*>(qw);
        for (int i = tid; i < 4096; i += 256) {
            int keyw = i & 31;           // word index (keys 2w, 2w+1)
            int rest = i >> 5;           // h*32 + dd
            int h2 = rest >> 5, dd = rest & 31;
            const __nv_bfloat16* src = qb + h2 * 96 + 64 + dd;
            uint16_t lo = *reinterpret_cast<const uint16_t*>(src + (keyw * 2) * 392);
            uint16_t hi = *reinterpret_cast<const uint16_t*>(src + (keyw * 2 + 1) * 392);
            bW[rest * SBW64 + keyw] = (uint32_t)lo | ((uint32_t)hi << 16);
        }
    }
    __syncthreads();

    // ---- Phase 3: attention (register-resident P) ----
    int h = wid >> 1;
    int rbase = (wid & 1) * 32;
    int qh = h * 48, kh = h * 48 + 16;
    const uint32_t* vth = bW + h * (32 * SBW64);
    const float scale = 0.17677669529663687f;

    {
        float c[2][8][4];
#pragma unroll
        for (int i = 0; i < 2; i++)
#pragma unroll
            for (int j = 0; j < 8; j++)
#pragma unroll
                for (int q = 0; q < 4; q++) c[i][j][q] = 0.0f;

#pragma unroll
        for (int kq = 0; kq < 2; kq++) {
            uint32_t a[2][4], b[8][2];
#pragma unroll
            for (int i = 0; i < 2; i++) {
                int row = rbase + i * 16 + g;
                a[i][0] = qw[row * QW4 + qh + kq * 8 + tg];
                a[i][1] = qw[(row + 8) * QW4 + qh + kq * 8 + tg];
                a[i][2] = qw[row * QW4 + qh + kq * 8 + tg + 4];
                a[i][3] = qw[(row + 8) * QW4 + qh + kq * 8 + tg + 4];
            }
#pragma unroll
            for (int j = 0; j < 8; j++) {
                int n = j * 8 + g;
                b[j][0] = qw[n * QW4 + kh + kq * 8 + tg];
                b[j][1] = qw[n * QW4 + kh + kq * 8 + tg + 4];
            }
#pragma unroll
            for (int i = 0; i < 2; i++)
#pragma unroll
                for (int j = 0; j < 8; j++)
                    mma_bf16(c[i][j], a[i], b[j]);
        }

        unsigned mask = 0;
#pragma unroll
        for (int j = 0; j < 8; j++)
#pragma unroll
            for (int q = 0; q < 2; q++)
                if (kfl[j * 8 + 2 * tg + q] == 2) mask |= 1u << (j * 2 + q);

#pragma unroll
        for (int i = 0; i < 2; i++)
#pragma unroll
            for (int sel = 0; sel < 2; sel++) {
                float mx = -1e30f;
#pragma unroll
                for (int j = 0; j < 8; j++)
#pragma unroll
                    for (int q = 0; q < 2; q++) {
                        float v = c[i][j][sel * 2 + q] * scale;
                        if (mask & (1u << (j * 2 + q))) v = -10000.0f;
                        c[i][j][sel * 2 + q] = v;
                        mx = fmaxf(mx, v);
                    }
                mx = fmaxf(mx, __shfl_xor_sync(0xffffffffu, mx, 1));
                mx = fmaxf(mx, __shfl_xor_sync(0xffffffffu, mx, 2));
                float s = 0.0f;
#pragma unroll
                for (int j = 0; j < 8; j++)
#pragma unroll
                    for (int q = 0; q < 2; q++) {
                        float e = __expf(c[i][j][sel * 2 + q] - mx);
                        c[i][j][sel * 2 + q] = e;
                        s += e;
                    }
                s += __shfl_xor_sync(0xffffffffu, s, 1);
                s += __shfl_xor_sync(0xffffffffu, s, 2);
                float rinv = 1.0f / s;
#pragma unroll
                for (int j = 0; j < 8; j++)
#pragma unroll
                    for (int q = 0; q < 2; q++)
                        c[i][j][sel * 2 + q] *= rinv;
            }

        float o[2][4][4];
#pragma unroll
        for (int i = 0; i < 2; i++)
#pragma unroll
            for (int j = 0; j < 4; j++)
#pragma unroll
                for (int q = 0; q < 4; q++) o[i][j][q] = 0.0f;

#pragma unroll
        for (int kp = 0; kp < 4; kp++) {
            uint32_t b[4][2];
#pragma unroll
            for (int j = 0; j < 4; j++) {
                int n = j * 8 + g;
                b[j][0] = vth[n * SBW64 + kp * 8 + tg];
                b[j][1] = vth[n * SBW64 + kp * 8 + tg + 4];
            }
#pragma unroll
            for (int i = 0; i < 2; i++) {
                uint32_t a[4];
                a[0] = packbf(c[i][2 * kp][0],     c[i][2 * kp][1]);
                a[1] = packbf(c[i][2 * kp][2],     c[i][2 * kp][3]);
                a[2] = packbf(c[i][2 * kp + 1][0], c[i][2 * kp + 1][1]);
                a[3] = packbf(c[i][2 * kp + 1][2], c[i][2 * kp + 1][3]);
#pragma unroll
                for (int j = 0; j < 4; j++)
                    mma_bf16(o[i][j], a, b[j]);
            }
        }

        // O into xpw (xp panel dead after QKV)
#pragma unroll
        for (int i = 0; i < 2; i++)
#pragma unroll
            for (int j = 0; j < 4; j++) {
                int row = rbase + i * 16 + g;
                int wrd = h * 16 + j * 4 + tg;
                xpw[row * SAW + wrd]       = packbf(o[i][j][0], o[i][j][1]);
                xpw[(row + 8) * SAW + wrd] = packbf(o[i][j][2], o[i][j][3]);
            }
    }
    __syncthreads();     // VT dead beyond this point

    // ---- Phase 4: proj GEMM (64x128, 2 k64-chunks) + scatter ----
    {
        float pc[2][4][4];
#pragma unroll
        for (int i = 0; i < 2; i++)
#pragma unroll
            for (int j = 0; j < 4; j++)
#pragma unroll
                for (int q = 0; q < 4; q++) pc[i][j][q] = 0.0f;

#pragma unroll
        for (int kc = 0; kc < 2; kc++) {
            int s = kc ^ 1;    // kc0 from stage1 (prefetched), kc1 from stage0
            if (kc == 0) {
                loadPB(1, 0);
                asm volatile("cp.async.wait_group 1;" ::: "memory");
            } else {
                asm volatile("cp.async.wait_group 0;" ::: "memory");
            }
            __syncthreads();
            const uint32_t* Bp = bW + s * BST64;
#pragma unroll
            for (int kk = 0; kk < 4; kk++) {
                int kwA = kc * 32 + kk * 8 + tg;
                int kwB = kk * 8 + tg;
                uint32_t a[2][4], b[4][2];
#pragma unroll
                for (int i = 0; i < 2; i++) {
                    int row = wr2 * 32 + i * 16 + g;
                    a[i][0] = xpw[row * SAW + kwA];
                    a[i][1] = xpw[(row + 8) * SAW + kwA];
                    a[i][2] = xpw[row * SAW + kwA + 4];
                    a[i][3] = xpw[(row + 8) * SAW + kwA + 4];
                }
#pragma unroll
                for (int j = 0; j < 4; j++) {
                    int n = wc2 * 32 + j * 8 + g;
                    b[j][0] = Bp[n * SBW64 + kwB];
                    b[j][1] = Bp[n * SBW64 + kwB + 4];
                }
#pragma unroll
                for (int i = 0; i < 2; i++)
#pragma unroll
                    for (int j = 0; j < 4; j++)
                        mma_bf16(pc[i][j], a[i], b[j]);
            }
            if (kc == 0) __syncthreads();
        }

#pragma unroll
        for (int i = 0; i < 2; i++)
#pragma unroll
            for (int half = 0; half < 2; half++) {
                int lrow = wr2 * 32 + i * 16 + g + half * 8;
                size_t grow = r0 + lrow;
                int f = kfl[lrow];
                if (f == 2) continue;
                if (f == 1) {
                    size_t rank = (size_t)g_mrank[grow];
#pragma unroll
                    for (int j = 0; j < 4; j++) {
                        int colg = wc2 * 32 + j * 8 + tg * 2;
                        float v0 = pc[i][j][half * 2]     + __ldg(&projb[colg]);
                        float v1 = pc[i][j][half * 2 + 1] + __ldg(&projb[colg + 1]);
                        v0 = g_xa[rank * C_DIM + colg]     + __ldg(&g1[colg]) * v0;
                        v1 = g_xa[rank * C_DIM + colg + 1] + __ldg(&g1[colg + 1]) * v1;
                        *reinterpret_cast<float2*>(g_y + rank * C_DIM + colg) =
                            make_float2(v0, v1);
                    }
                } else {
                    float* dstf = outv + (size_t)g_mrow[grow] * C_DIM;
#pragma unroll
                    for (int j = 0; j < 4; j++) {
                        int colg = wc2 * 32 + j * 8 + tg * 2;
                        float v0 = pc[i][j][half * 2]     + __ldg(&projb[colg]);
                        float v1 = pc[i][j][half * 2 + 1] + __ldg(&projb[colg + 1]);
                        *reinterpret_cast<float2*>(dstf + colg) = make_float2(v0, v1);
                    }
                }
            }
    }
}

// ---------------------------------------------------------------------------
// mlpf: LN2 -> MLP1(gelu) -> MLP2 + residual scatter, block = 64 asy rows.
// Cross-n-chunk prefetch in MLP1 + MLP2-k0 prefetch at MLP1 tail.
// ---------------------------------------------------------------------------
#define SHW 260
#define SBW 20
#define BSTG (128 * SBW)            // 2560-word k32 stage (MLP1)
#define MF_A_OFF 0
#define MF_H_OFF 4608
#define MF_B_OFF (MF_H_OFF + 64 * SHW)
#define MF_SMEM_BYTES ((MF_B_OFF + 2 * BSTG) * 4)

__global__ void __launch_bounds__(256) mlpf_kernel(
    const __nv_bfloat16* __restrict__ W1T, const float* __restrict__ b1,
    const __nv_bfloat16* __restrict__ W2T, const float* __restrict__ b2,
    const float* __restrict__ ln2w, const float* __restrict__ ln2b,
    const float* __restrict__ g2, float* __restrict__ outv)
{
    extern __shared__ uint32_t smu[];
    uint32_t* aw = smu + MF_A_OFF;
    uint32_t* hw = smu + MF_H_OFF;
    uint32_t* bW = smu + MF_B_OFF;

    int tid  = threadIdx.x;
    int lane = tid & 31;
    int wid  = tid >> 5;
    int g    = lane >> 2;
    int tg   = lane & 3;
    int wr2  = wid >> 2;
    int wc2  = wid & 3;
    size_t m0 = (size_t)blockIdx.x * 64;

    uint32_t smu_u = smem_u32(smu);
    uint32_t b_u = smu_u + MF_B_OFF * 4;

    auto loadB1 = [&](int nc, int kc, int s) {
#pragma unroll
        for (int t = 0; t < 2; t++) {
            int idx = tid + t * 256;
            int r = idx >> 2, cc = idx & 3;
            cp_async16(b_u + (uint32_t)(s * (BSTG * 4) + r * (SBW * 4) + cc * 16),
                       W1T + (size_t)(nc * 128 + r) * C_DIM + kc * 32 + cc * 8);
        }
        asm volatile("cp.async.commit_group;" ::: "memory");
    };
    // MLP2 k64 loader: s==0 -> bW region, s==1 -> aw region (aw dead)
    auto loadB2 = [&](int kc, int s) {
        uint32_t base = s ? smu_u : b_u;
#pragma unroll
        for (int t = 0; t < 4; t++) {
            int idx = tid + t * 256;
            int r = idx >> 3, cc = idx & 7;
            cp_async16(base + (uint32_t)(r * (SBW64 * 4) + cc * 16),
                       W2T + (size_t)r * 512 + kc * 64 + cc * 8);
        }
        asm volatile("cp.async.commit_group;" ::: "memory");
    };

    loadB1(0, 0, 0);

    // LN2 over g_y -> bf16 A panel (warp per 8 rows)
    {
        float4 wv = reinterpret_cast<const float4*>(ln2w)[lane];
        float4 bv = reinterpret_cast<const float4*>(ln2b)[lane];
        for (int it = 0; it < 8; it++) {
            int r = wid * 8 + it;
            float4 v = reinterpret_cast<const float4*>(g_y + (m0 + r) * C_DIM)[lane];
            float s1 = v.x + v.y + v.z + v.w;
            float s2 = v.x*v.x + v.y*v.y + v.z*v.z + v.w*v.w;
            warp_sum2(s1, s2);
            float m = s1 * (1.0f / C_DIM);
            float var = s2 * (1.0f / C_DIM) - m * m;
            float inv = rsqrtf(var + EPS_LN);
            aw[r * SAW + lane * 2] = packbf(
                (v.x - m) * inv * wv.x + bv.x, (v.y - m) * inv * wv.y + bv.y);
            aw[r * SAW + lane * 2 + 1] = packbf(
                (v.z - m) * inv * wv.z + bv.z, (v.w - m) * inv * wv.w + bv.w);
        }
    }

    // ---- MLP1: 4 n-chunks, k32 double-buffered, cross-nc prefetch ----
#pragma unroll 1
    for (int nc = 0; nc < 4; nc++) {
        float pc[2][4][4];
#pragma unroll
        for (int i = 0; i < 2; i++)
#pragma unroll
            for (int j = 0; j < 4; j++)
#pragma unroll
                for (int q = 0; q < 4; q++) pc[i][j][q] = 0.0f;

#pragma unroll
        for (int kc = 0; kc < 4; kc++) {
            int s = kc & 1;
            if (kc < 3) {
                loadB1(nc, kc + 1, s ^ 1);
                asm volatile("cp.async.wait_group 1;" ::: "memory");
            } else {
                if (nc < 3) loadB1(nc + 1, 0, s ^ 1);
                else        loadB2(0, 0);       // prefetch MLP2 k0 into bW base
                asm volatile("cp.async.wait_group 1;" ::: "memory");
            }
            __syncthreads();
            const uint32_t* Bp = bW + s * BSTG;
#pragma unroll
            for (int kk = 0; kk < 2; kk++) {
                int kw = kc * 16 + kk * 8 + tg;
                uint32_t a[2][4], b[4][2];
#pragma unroll
                for (int i = 0; i < 2; i++) {
                    int row = wr2 * 32 + i * 16 + g;
                    a[i][0] = aw[row * SAW + kw];
                    a[i][1] = aw[(row + 8) * SAW + kw];
                    a[i][2] = aw[row * SAW + kw + 4];
                    a[i][3] = aw[(row + 8) * SAW + kw + 4];
                }
#pragma unroll
                for (int j = 0; j < 4; j++) {
                    int n = wc2 * 32 + j * 8 + g;
                    b[j][0] = Bp[n * SBW + kk * 8 + tg];
                    b[j][1] = Bp[n * SBW + kk * 8 + tg + 4];
                }
#pragma unroll
                for (int i = 0; i < 2; i++)
#pragma unroll
                    for (int j = 0; j < 4; j++)
                        mma_bf16(pc[i][j], a[i], b[j]);
            }
            __syncthreads();
        }
#pragma unroll
        for (int i = 0; i < 2; i++)
#pragma unroll
            for (int half = 0; half < 2; half++) {
                int row = wr2 * 32 + i * 16 + g + half * 8;
#pragma unroll
                for (int j = 0; j < 4; j++) {
                    int colg = nc * 128 + wc2 * 32 + j * 8 + tg * 2;
                    float v0 = pc[i][j][half * 2]     + __ldg(&b1[colg]);
                    float v1 = pc[i][j][half * 2 + 1] + __ldg(&b1[colg + 1]);
                    v0 = 0.5f * v0 * (1.0f + erff(v0 * 0.7071067811865476f));
                    v1 = 0.5f * v1 * (1.0f + erff(v1 * 0.7071067811865476f));
                    hw[row * SHW + (colg >> 1)] = packbf(v0, v1);
                }
            }
    }
    __syncthreads();

    // ---- MLP2: 64x128, K=512 as 8 k64-chunks (k0 prefetched above) ----
    {
        float pc[2][4][4];
#pragma unroll
        for (int i = 0; i < 2; i++)
#pragma unroll
            for (int j = 0; j < 4; j++)
#pragma unroll
                for (int q = 0; q < 4; q++) pc[i][j][q] = 0.0f;

#pragma unroll 1
        for (int kc = 0; kc < 8; kc++) {
            int s = kc & 1;
            if (kc + 1 < 8) {
                loadB2(kc + 1, s ^ 1);
                asm volatile("cp.async.wait_group 1;" ::: "memory");
            } else {
                asm volatile("cp.async.wait_group 0;" ::: "memory");
            }
            __syncthreads();
            const uint32_t* Bp = s ? smu : bW;
#pragma unroll
            for (int kk = 0; kk < 4; kk++) {
                int kwA = kc * 32 + kk * 8 + tg;
                int kwB = kk * 8 + tg;
                uint32_t a[2][4], b[4][2];
#pragma unroll
                for (int i = 0; i < 2; i++) {
                    int row = wr2 * 32 + i * 16 + g;
                    a[i][0] = hw[row * SHW + kwA];
                    a[i][1] = hw[(row + 8) * SHW + kwA];
                    a[i][2] = hw[row * SHW + kwA + 4];
                    a[i][3] = hw[(row + 8) * SHW + kwA + 4];
                }
#pragma unroll
                for (int j = 0; j < 4; j++) {
                    int n = wc2 * 32 + j * 8 + g;
                    b[j][0] = Bp[n * SBW64 + kwB];
                    b[j][1] = Bp[n * SBW64 + kwB + 4];
                }
#pragma unroll
                for (int i = 0; i < 2; i++)
#pragma unroll
                    for (int j = 0; j < 4; j++)
                        mma_bf16(pc[i][j], a[i], b[j]);
            }
            if (kc + 1 < 8) __syncthreads();
        }

#pragma unroll
        for (int i = 0; i < 2; i++)
#pragma unroll
            for (int half = 0; half < 2; half++) {
                size_t grow = m0 + wr2 * 32 + i * 16 + g + half * 8;
                float* dstf = outv + (size_t)g_asyrow[grow] * C_DIM;
#pragma unroll
                for (int j = 0; j < 4; j++) {
                    int colg = wc2 * 32 + j * 8 + tg * 2;
                    float v0 = pc[i][j][half * 2]     + __ldg(&b2[colg]);
                    float v1 = pc[i][j][half * 2 + 1] + __ldg(&b2[colg + 1]);
                    v0 = g_y[grow * C_DIM + colg]     + __ldg(&g2[colg]) * v0;
                    v1 = g_y[grow * C_DIM + colg + 1] + __ldg(&g2[colg + 1]) * v1;
                    *reinterpret_cast<float2*>(dstf + colg) = make_float2(v0, v1);
                }
            }
    }
}

// ---------------------------------------------------------------------------
extern "C" void kernel_launch(void* const* d_in, const int* in_sizes, int n_in,
                              void* d_out, int out_size)
{
    int base = 7;
    if (n_in == 19) base = 5;

    const float* x      = (const float*)d_in[0];
    const int*   iw     = (const int*)d_in[1];
    const int*   ipart  = (const int*)d_in[2];
    const int*   asy    = (const int*)d_in[3];
    const int*   blk    = (const int*)d_in[4];
    const float* ln1w   = (const float*)d_in[base + 0];
    const float* ln1b   = (const float*)d_in[base + 1];
    const float* qkvw   = (const float*)d_in[base + 2];
    const float* qkvb   = (const float*)d_in[base + 3];
    const float* projw  = (const float*)d_in[base + 4];
    const float* projb  = (const float*)d_in[base + 5];
    const float* g1     = (const float*)d_in[base + 6];
    const float* ln2w   = (const float*)d_in[base + 7];
    const float* ln2b   = (const float*)d_in[base + 8];
    const float* w1     = (const float*)d_in[base + 9];
    const float* b1     = (const float*)d_in[base + 10];
    const float* w2     = (const float*)d_in[base + 11];
    const float* b2     = (const float*)d_in[base + 12];
    const float* g2     = (const float*)d_in[base + 13];
    float* out = (float*)d_out;

    __nv_bfloat16 *p_xp, *p_wqkvT, *p_wprojT, *p_w1T, *p_w2T;
    cudaGetSymbolAddress((void**)&p_xp, g_xp_bf);
    cudaGetSymbolAddress((void**)&p_wqkvT, g_wqkvT);
    cudaGetSymbolAddress((void**)&p_wprojT, g_wprojT);
    cudaGetSymbolAddress((void**)&p_w1T, g_w1T);
    cudaGetSymbolAddress((void**)&p_w2T, g_w2T);

    cudaFuncSetAttribute(qap_kernel,
                         cudaFuncAttributeMaxDynamicSharedMemorySize, QP_SMEM_BYTES);
    cudaFuncSetAttribute(mlpf_kernel,
                         cudaFuncAttributeMaxDynamicSharedMemorySize, MF_SMEM_BYTES);

    // 0-2. init + maps + meta + merged weight transpose
    zero_misc_kernel<<<(MW_CNT / 16 + N_WIN / 4 + 255) / 256, 256>>>();
    set_maps_kernel<<<MW_CNT / 256, 256>>>(asy, blk, iw, ipart);
    meta_kernel<<<MW_CNT / 256, 256>>>(ipart, iw);
    wtrans_all_kernel<<<768, 256>>>(qkvw, projw, w1, w2,
                                    p_wqkvT, p_wprojT, p_w1T, p_w2T);
    // 3. fused LN + double-LN + scatter
    ln_kernel<<<N_TOK / 16, 256>>>(x, ln1w, ln1b, out);
    // 4. QKV -> attention -> proj fused (per partition)
    qap_kernel<<<M_PART, 256, QP_SMEM_BYTES>>>(
        p_xp, p_wqkvT, qkvb, p_wprojT, projb, g1, out);
    // 5. LN2 -> MLP1 -> MLP2 fused (per 64 asy rows)
    mlpf_kernel<<<A_CNT / 64, 256, MF_SMEM_BYTES>>>(
        p_w1T, b1, p_w2T, b2, ln2w, ln2b, g2, out);
}